// round 4
// baseline (speedup 1.0000x reference)
#include <cuda_runtime.h>
#include <cuda_bf16.h>
#include <math.h>

#define N_NODES 200000
#define N_DEST  8192
#define N_EDGE  262144
#define D_MEM   128
#define D_FEAT  128
#define D_EDGE  64
#define D_TIME  32
#define D_MSG   128

// ---------------- scratch (device globals: allocation-free) ------------------
__device__ float g_msg_sum[N_DEST * D_MSG];   // zero-init; dest_kernel re-zeroes
__device__ float g_cnt[N_DEST];
__device__ unsigned g_Wh[15 * 2048];          // pre-split W_read(8)+W_msg(7) chunks
__device__ unsigned g_Wl[15 * 2048];          // packed bf16x2 hi/lo, [chunk][kp][128]

__device__ __forceinline__ int idx_at(const void* p, long long i, int is64) {
    return is64 ? (int)((const long long*)p)[i] : ((const int*)p)[i];
}

// ---------------- bf16 split-pack helpers ------------------------------------
// pack (x0,x1) -> bf16x2 hi (rn) and bf16x2 lo (residual); lower half = x0.
__device__ __forceinline__ void splitpack(float x0, float x1, unsigned& hi, unsigned& lo) {
    unsigned h;
    asm("cvt.rn.bf16x2.f32 %0, %1, %2;" : "=r"(h) : "f"(x1), "f"(x0));
    float h0 = __uint_as_float(h << 16);
    float h1 = __uint_as_float(h & 0xFFFF0000u);
    float r0 = x0 - h0;
    float r1 = x1 - h1;
    unsigned l;
    asm("cvt.rn.bf16x2.f32 %0, %1, %2;" : "=r"(l) : "f"(r1), "f"(r0));
    hi = h;
    lo = l;
}

__device__ __forceinline__ void mma_bf16(float* c, const unsigned* a, const unsigned* b) {
    asm volatile(
        "mma.sync.aligned.m16n8k16.row.col.f32.bf16.bf16.f32 "
        "{%0,%1,%2,%3},{%4,%5,%6,%7},{%8,%9},{%0,%1,%2,%3};"
        : "+f"(c[0]), "+f"(c[1]), "+f"(c[2]), "+f"(c[3])
        : "r"(a[0]), "r"(a[1]), "r"(a[2]), "r"(a[3]), "r"(b[0]), "r"(b[1]));
}

// ---------------- prep: pre-split weights into bf16x2 hi/lo -------------------
__global__ void prep_kernel(const float* __restrict__ W_read,
                            const float* __restrict__ W_msg) {
    const int idx = blockIdx.x * blockDim.x + threadIdx.x;
    if (idx >= 15 * 2048) return;
    const int chunk = idx >> 11;
    const int kp = (idx >> 7) & 15;
    const int c = idx & 127;
    const float* W = (chunk < 8) ? (W_read + chunk * 32 * 128)
                                 : (W_msg + (chunk - 8) * 32 * 128);
    const float x0 = W[(2 * kp) * 128 + c];
    const float x1 = W[(2 * kp + 1) * 128 + c];
    unsigned h, l;
    splitpack(x0, x1, h, l);
    g_Wh[idx] = h;
    g_Wl[idx] = l;
}

// ---------------- edge kernel layout ------------------------------------------
#define PA 20    // A buf stride (conflict-free: 20*gid + tig distinct mod 32)
#define PW 136   // W buf stride (8*tig + 8*nf + gid distinct mod 32)
#define PS 116   // stage stride (116 mod 32 = 20, same class as A)
#define STRIDE_M 132

// smem u32 offsets
#define O_AH0 0
#define O_AL0 2560
#define O_AH1 5120
#define O_AL1 7680
#define O_WH0 10240
#define O_WL0 12416
#define O_WH1 14592
#define O_WL1 16768
#define O_SH  18944
#define O_SL  33792
#define EDGE_U32 48640
#define EDGE_SMEM (EDGE_U32 * 4)

__device__ __forceinline__ void flush_seg(int d, int tx, const float* r, float rl) {
    float* p = g_msg_sum + (size_t)d * D_MSG + tx * 4;
    atomicAdd(p + 0, r[0]);
    atomicAdd(p + 1, r[1]);
    atomicAdd(p + 2, r[2]);
    atomicAdd(p + 3, r[3]);
    if (tx == 0) atomicAdd(&g_cnt[d], rl);
}

// one K=32 chunk of 3-term bf16 mma: A hi/lo [rows][strideA], W hi/lo [16][PW]
__device__ __forceinline__ void mma_k32(const unsigned* __restrict__ Ah,
                                        const unsigned* __restrict__ Al, int strideA,
                                        const unsigned* __restrict__ Wh,
                                        const unsigned* __restrict__ Wl,
                                        int r0, int c0, int gid, int tig,
                                        float acc[2][4][4]) {
#pragma unroll
    for (int half = 0; half < 2; half++) {
        const int kb = half * 8;
        unsigned ah[2][4], al[2][4];
#pragma unroll
        for (int mf = 0; mf < 2; mf++) {
            const int ra = r0 + mf * 16 + gid;
            ah[mf][0] = Ah[ra * strideA + kb + tig];
            ah[mf][1] = Ah[(ra + 8) * strideA + kb + tig];
            ah[mf][2] = Ah[ra * strideA + kb + tig + 4];
            ah[mf][3] = Ah[(ra + 8) * strideA + kb + tig + 4];
            al[mf][0] = Al[ra * strideA + kb + tig];
            al[mf][1] = Al[(ra + 8) * strideA + kb + tig];
            al[mf][2] = Al[ra * strideA + kb + tig + 4];
            al[mf][3] = Al[(ra + 8) * strideA + kb + tig + 4];
        }
#pragma unroll
        for (int nf = 0; nf < 4; nf++) {
            const int col = c0 + nf * 8 + gid;
            unsigned bh[2], bl[2];
            bh[0] = Wh[(kb + tig) * PW + col];
            bh[1] = Wh[(kb + tig + 4) * PW + col];
            bl[0] = Wl[(kb + tig) * PW + col];
            bl[1] = Wl[(kb + tig + 4) * PW + col];
#pragma unroll
            for (int mf = 0; mf < 2; mf++) {
                mma_bf16(acc[mf][nf], ah[mf], bh);
                mma_bf16(acc[mf][nf], ah[mf], bl);
                mma_bf16(acc[mf][nf], al[mf], bh);
            }
        }
    }
}

__global__ __launch_bounds__(512, 1) void edge_kernel(
    const float* __restrict__ node_memory, const float* __restrict__ node_features,
    const float* __restrict__ edge_features, const float* __restrict__ time_encoding,
    const void* __restrict__ node_ids,
    const void* __restrict__ source_ids, const void* __restrict__ edge_ids,
    const void* __restrict__ dest_seg,
    const float* __restrict__ b_read, const float* __restrict__ b_msg,
    float* __restrict__ out) {
    extern __shared__ unsigned su[];
    unsigned* bAh[2] = {su + O_AH0, su + O_AH1};
    unsigned* bAl[2] = {su + O_AL0, su + O_AL1};
    unsigned* bWh[2] = {su + O_WH0, su + O_WH1};
    unsigned* bWl[2] = {su + O_WL0, su + O_WL1};
    unsigned* sSh = su + O_SH;
    unsigned* sSl = su + O_SL;
    __shared__ int s_src[128], s_eid[128], s_dst[128];

    const int tid = threadIdx.x;
    const int lane = tid & 31;
    const int warp = tid >> 5;
    const int gid = lane >> 2;
    const int tig = lane & 3;
    const int r0 = (warp >> 2) * 32;
    const int c0 = (warp & 3) * 32;
    const long long ebase = (long long)blockIdx.x * 128;

    const unsigned* nw = (const unsigned*)node_ids;
    const int is64 = (nw[1] == 0u && nw[3] == 0u);

    if (tid < 128) {
        s_src[tid] = idx_at(source_ids, ebase + tid, is64);
        s_eid[tid] = idx_at(edge_ids, ebase + tid, is64);
        s_dst[tid] = idx_at(dest_seg, ebase + tid, is64);
    }
    __syncthreads();

    const int arow = tid >> 2;   // fill row 0..127
    const int aq = tid & 3;      // fill quarter
    const int wkp = tid >> 5;    // W fill kpair
    const int wc4 = (tid & 31) * 4;

    // ---- fill helpers (macro-ish lambdas) ----
    float4 a0r, a1r;
    uint4 whr, wlr;
    auto ldA = [&](int kc) {
        const float* base = (kc < 4)
            ? node_memory + (size_t)s_src[arow] * D_MEM + kc * 32
            : node_features + (size_t)s_src[arow] * D_FEAT + (kc - 4) * 32;
        const float4* b4 = (const float4*)base;
        a0r = b4[aq * 2];
        a1r = b4[aq * 2 + 1];
    };
    auto ldW = [&](int gchunk) {
        whr = *(const uint4*)(g_Wh + gchunk * 2048 + tid * 4);
        wlr = *(const uint4*)(g_Wl + gchunk * 2048 + tid * 4);
    };
    auto stA = [&](int buf) {
        unsigned h0, l0, h1, l1, h2, l2, h3, l3;
        splitpack(a0r.x, a0r.y, h0, l0);
        splitpack(a0r.z, a0r.w, h1, l1);
        splitpack(a1r.x, a1r.y, h2, l2);
        splitpack(a1r.z, a1r.w, h3, l3);
        *(uint4*)(bAh[buf] + arow * PA + aq * 4) = make_uint4(h0, h1, h2, h3);
        *(uint4*)(bAl[buf] + arow * PA + aq * 4) = make_uint4(l0, l1, l2, l3);
    };
    auto stW = [&](int buf) {
        *(uint4*)(bWh[buf] + wkp * PW + wc4) = whr;
        *(uint4*)(bWl[buf] + wkp * PW + wc4) = wlr;
    };

    // initial prefetch: A chunk 0, W chunk 0 (global chunk 0)
    ldA(0);
    ldW(0);

    // prefill stage kpairs [64,112): edge feats (64..95), time (96..111)
    {
        const float4* ef = (const float4*)(edge_features + (size_t)s_eid[arow] * D_EDGE);
#pragma unroll
        for (int j = 0; j < 4; j++) {
            float4 v = ef[aq * 4 + j];
            unsigned h0, l0, h1, l1;
            splitpack(v.x, v.y, h0, l0);
            splitpack(v.z, v.w, h1, l1);
            const int pi = 64 + aq * 8 + 2 * j;
            sSh[arow * PS + pi] = h0;     sSl[arow * PS + pi] = l0;
            sSh[arow * PS + pi + 1] = h1; sSl[arow * PS + pi + 1] = l1;
        }
        const float4* tf = (const float4*)(time_encoding + (ebase + arow) * D_TIME);
#pragma unroll
        for (int j = 0; j < 2; j++) {
            float4 v = tf[aq * 2 + j];
            unsigned h0, l0, h1, l1;
            splitpack(v.x, v.y, h0, l0);
            splitpack(v.z, v.w, h1, l1);
            const int pi = 96 + aq * 4 + 2 * j;
            sSh[arow * PS + pi] = h0;     sSl[arow * PS + pi] = l0;
            sSh[arow * PS + pi + 1] = h1; sSl[arow * PS + pi + 1] = l1;
        }
    }

    // store chunk 0 into buffer 0
    stA(0);
    stW(0);
    __syncthreads();

    float acc[2][4][4];
#pragma unroll
    for (int m = 0; m < 2; m++)
#pragma unroll
        for (int n = 0; n < 4; n++)
#pragma unroll
            for (int c = 0; c < 4; c++) acc[m][n][c] = 0.f;

    // ---- Phase 1: src_read = relu([mem|feat] @ W_read + b), K=256, pipelined ----
    for (int kc = 0; kc < 8; kc++) {
        const int cur = kc & 1, nxt = cur ^ 1;
        if (kc < 7) {
            ldA(kc + 1);
            ldW(kc + 1);
        } else {
            ldW(8);   // phase-2 chunk 0
        }
        mma_k32(bAh[cur], bAl[cur], PA, bWh[cur], bWl[cur], r0, c0, gid, tig, acc);
        if (kc < 7) {
            stA(nxt);
            stW(nxt);
        } else {
            stW(nxt);
        }
        __syncthreads();
    }

    // ---- Phase 1 epilogue: bias+relu -> stage kpairs [0,64) ----
#pragma unroll
    for (int mf = 0; mf < 2; mf++) {
        const int ra = r0 + mf * 16 + gid;
#pragma unroll
        for (int nf = 0; nf < 4; nf++) {
            const int col = c0 + nf * 8 + 2 * tig;
            const int pi = col >> 1;
            const float bb0 = b_read[col], bb1 = b_read[col + 1];
            unsigned h, l;
            float v0 = fmaxf(acc[mf][nf][0] + bb0, 0.f);
            float v1 = fmaxf(acc[mf][nf][1] + bb1, 0.f);
            splitpack(v0, v1, h, l);
            sSh[ra * PS + pi] = h;
            sSl[ra * PS + pi] = l;
            v0 = fmaxf(acc[mf][nf][2] + bb0, 0.f);
            v1 = fmaxf(acc[mf][nf][3] + bb1, 0.f);
            splitpack(v0, v1, h, l);
            sSh[(ra + 8) * PS + pi] = h;
            sSl[(ra + 8) * PS + pi] = l;
        }
    }
    __syncthreads();

    // ---- Phase 2: msgs = relu([src_read|ef|time] @ W_msg + b), K=224, pipelined ----
#pragma unroll
    for (int m = 0; m < 2; m++)
#pragma unroll
        for (int n = 0; n < 4; n++)
#pragma unroll
            for (int c = 0; c < 4; c++) acc[m][n][c] = 0.f;

    for (int kc = 0; kc < 7; kc++) {
        const int cur = kc & 1, nxt = cur ^ 1;
        if (kc < 6) ldW(9 + kc);
        mma_k32(sSh + kc * 16, sSl + kc * 16, PS, bWh[cur], bWl[cur], r0, c0, gid, tig, acc);
        if (kc < 6) stW(nxt);
        __syncthreads();
    }

    // ---- Phase 2 epilogue: msgs -> msgbuf fp32 (reuse stage area) ----
    float* msg = (float*)(su + O_SH);   // [128][STRIDE_M]
#pragma unroll
    for (int mf = 0; mf < 2; mf++) {
        const int ra = r0 + mf * 16 + gid;
#pragma unroll
        for (int nf = 0; nf < 4; nf++) {
            const int col = c0 + nf * 8 + 2 * tig;
            const float b0 = b_msg[col], b1 = b_msg[col + 1];
            msg[ra * STRIDE_M + col]           = fmaxf(acc[mf][nf][0] + b0, 0.f);
            msg[ra * STRIDE_M + col + 1]       = fmaxf(acc[mf][nf][1] + b1, 0.f);
            msg[(ra + 8) * STRIDE_M + col]     = fmaxf(acc[mf][nf][2] + b0, 0.f);
            msg[(ra + 8) * STRIDE_M + col + 1] = fmaxf(acc[mf][nf][3] + b1, 0.f);
        }
    }
    __syncthreads();

    // ---- run-coalesced segment-sum atomics (dest_seg globally sorted) ----
    {
        const int tx = lane;
        const int e0 = warp * 8;
        int curd = s_dst[e0];
        float r[4] = {0.f, 0.f, 0.f, 0.f};
        float rl = 0.f;
#pragma unroll
        for (int i = 0; i < 8; i++) {
            const int e = e0 + i;
            const int d = s_dst[e];
            const float4 v = *(const float4*)(msg + e * STRIDE_M + tx * 4);
            if (d != curd) {
                flush_seg(curd, tx, r, rl);
                curd = d;
                r[0] = r[1] = r[2] = r[3] = 0.f;
                rl = 0.f;
            }
            r[0] += v.x; r[1] += v.y; r[2] += v.z; r[3] += v.w;
            rl += 1.f;
        }
        flush_seg(curd, tx, r, rl);
    }

    // ---- node_memory -> out copy slice (rides under compute of other blocks) ----
    {
        const float4* srcm = (const float4*)node_memory;
        float4* dstm = (float4*)out;
        const long long tot = (long long)N_NODES * D_MEM / 4;
        for (long long i = (long long)blockIdx.x * blockDim.x + tid; i < tot;
             i += (long long)gridDim.x * blockDim.x)
            dstm[i] = srcm[i];
    }
}

// ---------------- dest pipeline (fp32, proven; + self-zeroing) ----------------
#define TILE_E 64

__device__ __forceinline__ void mma_chunk(const float* __restrict__ Asub, int strideA,
                                          const float* __restrict__ Ws,
                                          int ty, int tx, float acc[8][4]) {
#pragma unroll
    for (int k = 0; k < 32; k++) {
        const float* arow = Asub + k * strideA + ty * 8;
        float4 a0 = *(const float4*)(arow);
        float4 a1 = *(const float4*)(arow + 4);
        float4 w  = *(const float4*)(Ws + k * 128 + tx * 4);
        float av[8] = {a0.x, a0.y, a0.z, a0.w, a1.x, a1.y, a1.z, a1.w};
#pragma unroll
        for (int i = 0; i < 8; i++) {
            acc[i][0] = fmaf(av[i], w.x, acc[i][0]);
            acc[i][1] = fmaf(av[i], w.y, acc[i][1]);
            acc[i][2] = fmaf(av[i], w.z, acc[i][2]);
            acc[i][3] = fmaf(av[i], w.w, acc[i][3]);
        }
    }
}

__device__ __forceinline__ void load_w(float* Ws, const float* __restrict__ Wsrc, int tid) {
    const float4* s = (const float4*)Wsrc;
    float4* d = (float4*)Ws;
#pragma unroll
    for (int i = 0; i < 4; i++) d[tid + i * 256] = s[tid + i * 256];
}

__device__ __forceinline__ void zero_acc(float acc[8][4]) {
#pragma unroll
    for (int i = 0; i < 8; i++)
#pragma unroll
        for (int c = 0; c < 4; c++) acc[i][c] = 0.f;
}

__global__ __launch_bounds__(256) void dest_kernel(
    const float* __restrict__ node_memory, const float* __restrict__ node_features,
    const void* __restrict__ node_ids,
    const float* __restrict__ W_read, const float* __restrict__ b_read,
    const float* __restrict__ W_agg, const float* __restrict__ b_agg,
    const float* __restrict__ W_upd, const float* __restrict__ b_upd,
    const float* __restrict__ W_write, const float* __restrict__ b_write,
    float* __restrict__ out) {
    extern __shared__ float sm[];
    float* As = sm;             // [32][64]
    float* Ws = sm + 2048;      // [32][128]
    float* CT = sm + 6144;      // [256][68]
    float* DR = sm + 23552;     // [128][68]
    __shared__ int s_nid[TILE_E];

    const int tid = threadIdx.x;
    const int tx = tid & 31;
    const int ty = tid >> 5;
    const int eL = tid & 63;
    const int kq = tid >> 6;
    const int rbase = blockIdx.x * TILE_E;

    const unsigned* nw = (const unsigned*)node_ids;
    const int is64 = (nw[1] == 0u && nw[3] == 0u);

    if (tid < TILE_E) s_nid[tid] = idx_at(node_ids, rbase + tid, is64);

    float acc[8][4];
    zero_acc(acc);

    for (int kc = 0; kc < 8; kc++) {
        __syncthreads();
        {
            const float* row = (kc < 4)
                ? node_memory + (size_t)s_nid[eL] * D_MEM + kc * 32
                : node_features + (size_t)s_nid[eL] * D_FEAT + (kc - 4) * 32;
            float4 v0 = ((const float4*)row)[kq * 2];
            float4 v1 = ((const float4*)row)[kq * 2 + 1];
            int kb = kq * 8;
            As[(kb + 0) * 64 + eL] = v0.x; As[(kb + 1) * 64 + eL] = v0.y;
            As[(kb + 2) * 64 + eL] = v0.z; As[(kb + 3) * 64 + eL] = v0.w;
            As[(kb + 4) * 64 + eL] = v1.x; As[(kb + 5) * 64 + eL] = v1.y;
            As[(kb + 6) * 64 + eL] = v1.z; As[(kb + 7) * 64 + eL] = v1.w;
        }
        load_w(Ws, W_read + kc * 32 * 128, tid);
        __syncthreads();
        mma_chunk(As, 64, Ws, ty, tx, acc);
    }
    {
        float4 bb = *(const float4*)&b_read[tx * 4];
        __syncthreads();
#pragma unroll
        for (int i = 0; i < 8; i++) {
            int e = ty * 8 + i;
#pragma unroll
            for (int c = 0; c < 4; c++) {
                float bv = (c == 0) ? bb.x : (c == 1) ? bb.y : (c == 2) ? bb.z : bb.w;
                float v = fmaxf(acc[i][c] + bv, 0.f);
                CT[(tx * 4 + c) * 68 + e] = v;
                DR[(tx * 4 + c) * 68 + e] = v;
            }
        }
    }
    {
        int dg = rbase + eL;
        float inv = 1.0f / fmaxf(g_cnt[dg], 1.0f);
        const float4* srcp = (const float4*)(g_msg_sum + (size_t)dg * D_MSG + kq * 32);
#pragma unroll
        for (int j4 = 0; j4 < 8; j4++) {
            float4 v = srcp[j4];
            int kk = 128 + kq * 32 + j4 * 4;
            CT[(kk + 0) * 68 + eL] = v.x * inv; CT[(kk + 1) * 68 + eL] = v.y * inv;
            CT[(kk + 2) * 68 + eL] = v.z * inv; CT[(kk + 3) * 68 + eL] = v.w * inv;
        }
    }
    // re-zero the consumed scratch so graph replays stay deterministic
    __syncthreads();
    {
        int dg = rbase + eL;
        float4 z = {0.f, 0.f, 0.f, 0.f};
        float4* p = (float4*)(g_msg_sum + (size_t)dg * D_MSG + kq * 32);
#pragma unroll
        for (int j4 = 0; j4 < 8; j4++) p[j4] = z;
        if (kq == 0) g_cnt[dg] = 0.f;
    }

    zero_acc(acc);
    for (int kc = 0; kc < 8; kc++) {
        __syncthreads();
        load_w(Ws, W_agg + kc * 32 * 128, tid);
        __syncthreads();
        mma_chunk(CT + kc * 32 * 68, 68, Ws, ty, tx, acc);
    }
    __syncthreads();
    {
        float4 ba = *(const float4*)&b_agg[tx * 4];
#pragma unroll
        for (int i = 0; i < 8; i++) {
            int e = ty * 8 + i;
            CT[(tx * 4 + 0) * 68 + e] = fmaxf(acc[i][0] + ba.x, 0.f);
            CT[(tx * 4 + 1) * 68 + e] = fmaxf(acc[i][1] + ba.y, 0.f);
            CT[(tx * 4 + 2) * 68 + e] = fmaxf(acc[i][2] + ba.z, 0.f);
            CT[(tx * 4 + 3) * 68 + e] = fmaxf(acc[i][3] + ba.w, 0.f);
        }
#pragma unroll
        for (int j = 0; j < 32; j++) {
            int row = kq * 32 + j;
            CT[(128 + row) * 68 + eL] = DR[row * 68 + eL];
        }
    }

    zero_acc(acc);
    for (int kc = 0; kc < 8; kc++) {
        __syncthreads();
        load_w(Ws, W_upd + kc * 32 * 128, tid);
        __syncthreads();
        mma_chunk(CT + kc * 32 * 68, 68, Ws, ty, tx, acc);
    }
    __syncthreads();
    {
        float4 bu = *(const float4*)&b_upd[tx * 4];
#pragma unroll
        for (int i = 0; i < 8; i++) {
            int e = ty * 8 + i;
            DR[(tx * 4 + 0) * 68 + e] = fmaxf(acc[i][0] + bu.x, 0.f);
            DR[(tx * 4 + 1) * 68 + e] = fmaxf(acc[i][1] + bu.y, 0.f);
            DR[(tx * 4 + 2) * 68 + e] = fmaxf(acc[i][2] + bu.z, 0.f);
            DR[(tx * 4 + 3) * 68 + e] = fmaxf(acc[i][3] + bu.w, 0.f);
        }
    }

    zero_acc(acc);
    for (int kc = 0; kc < 4; kc++) {
        __syncthreads();
        load_w(Ws, W_write + kc * 32 * 128, tid);
        __syncthreads();
        mma_chunk(DR + kc * 32 * 68, 68, Ws, ty, tx, acc);
    }
    {
        float4 bw = *(const float4*)&b_write[tx * 4];
#pragma unroll
        for (int i = 0; i < 8; i++) {
            int e = ty * 8 + i;
            float4 o;
            o.x = tanhf(acc[i][0] + bw.x);
            o.y = tanhf(acc[i][1] + bw.y);
            o.z = tanhf(acc[i][2] + bw.z);
            o.w = tanhf(acc[i][3] + bw.w);
            *(float4*)(out + (size_t)s_nid[e] * D_MEM + tx * 4) = o;
        }
    }
}

// ---------------- launch ------------------------------------------------------
#define DEST_SMEM ((2048 + 4096 + 256 * 68 + 128 * 68) * 4)

extern "C" void kernel_launch(void* const* d_in, const int* in_sizes, int n_in,
                              void* d_out, int out_size) {
    const float* node_memory   = (const float*)d_in[0];
    const float* node_features = (const float*)d_in[1];
    const float* edge_features = (const float*)d_in[2];
    const float* time_encoding = (const float*)d_in[3];
    const void*  node_ids      = d_in[4];
    const void*  source_ids    = d_in[5];
    const void*  edge_ids      = d_in[6];
    const void*  dest_seg      = d_in[7];
    const float* W_read  = (const float*)d_in[8];
    const float* b_read  = (const float*)d_in[9];
    const float* W_msg   = (const float*)d_in[10];
    const float* b_msg   = (const float*)d_in[11];
    const float* W_agg   = (const float*)d_in[12];
    const float* b_agg   = (const float*)d_in[13];
    const float* W_upd   = (const float*)d_in[14];
    const float* b_upd   = (const float*)d_in[15];
    const float* W_write = (const float*)d_in[16];
    const float* b_write = (const float*)d_in[17];
    float* out = (float*)d_out;

    cudaFuncSetAttribute(edge_kernel, cudaFuncAttributeMaxDynamicSharedMemorySize, EDGE_SMEM);
    cudaFuncSetAttribute(dest_kernel, cudaFuncAttributeMaxDynamicSharedMemorySize, DEST_SMEM);

    prep_kernel<<<120, 256>>>(W_read, W_msg);

    edge_kernel<<<N_EDGE / 128, 512, EDGE_SMEM>>>(
        node_memory, node_features, edge_features, time_encoding, node_ids,
        source_ids, edge_ids, dest_seg, b_read, b_msg, out);

    dest_kernel<<<N_DEST / TILE_E, 256, DEST_SMEM>>>(
        node_memory, node_features, node_ids,
        W_read, b_read, W_agg, b_agg, W_upd, b_upd, W_write, b_write, out);
}

// round 5
// speedup vs baseline: 1.1360x; 1.1360x over previous
#include <cuda_runtime.h>
#include <cuda_bf16.h>
#include <math.h>

#define N_NODES 200000
#define N_DEST  8192
#define N_EDGE  262144
#define D_MEM   128
#define D_FEAT  128
#define D_EDGE  64
#define D_TIME  32
#define D_MSG   128

// ---------------- scratch (device globals: allocation-free) ------------------
__device__ float g_msg_sum[N_DEST * D_MSG];   // zero-init; dest_kernel re-zeroes
__device__ float g_cnt[N_DEST];
__device__ unsigned g_Wh[15 * 2048];          // pre-split W_read(8)+W_msg(7) chunks
__device__ unsigned g_Wl[15 * 2048];          // packed bf16x2 hi/lo, [chunk][kp][128]

__device__ __forceinline__ int idx_at(const void* p, long long i, int is64) {
    return is64 ? (int)((const long long*)p)[i] : ((const int*)p)[i];
}

// ---------------- bf16 split-pack helpers ------------------------------------
__device__ __forceinline__ void splitpack(float x0, float x1, unsigned& hi, unsigned& lo) {
    unsigned h;
    asm("cvt.rn.bf16x2.f32 %0, %1, %2;" : "=r"(h) : "f"(x1), "f"(x0));
    float h0 = __uint_as_float(h << 16);
    float h1 = __uint_as_float(h & 0xFFFF0000u);
    float r0 = x0 - h0;
    float r1 = x1 - h1;
    unsigned l;
    asm("cvt.rn.bf16x2.f32 %0, %1, %2;" : "=r"(l) : "f"(r1), "f"(r0));
    hi = h;
    lo = l;
}

__device__ __forceinline__ void mma_bf16(float* c, const unsigned* a, const unsigned* b) {
    asm volatile(
        "mma.sync.aligned.m16n8k16.row.col.f32.bf16.bf16.f32 "
        "{%0,%1,%2,%3},{%4,%5,%6,%7},{%8,%9},{%0,%1,%2,%3};"
        : "+f"(c[0]), "+f"(c[1]), "+f"(c[2]), "+f"(c[3])
        : "r"(a[0]), "r"(a[1]), "r"(a[2]), "r"(a[3]), "r"(b[0]), "r"(b[1]));
}

// ---------------- cp.async helpers --------------------------------------------
__device__ __forceinline__ void cp16(unsigned dst_smem, const void* src) {
    asm volatile("cp.async.cg.shared.global [%0], [%1], 16;"
                 :: "r"(dst_smem), "l"(src));
}
#define CP_COMMIT() asm volatile("cp.async.commit_group;")
#define CP_WAIT1()  asm volatile("cp.async.wait_group 1;")
#define CP_WAIT0()  asm volatile("cp.async.wait_group 0;")

// ---------------- prep: pre-split weights into bf16x2 hi/lo -------------------
__global__ void prep_kernel(const float* __restrict__ W_read,
                            const float* __restrict__ W_msg) {
    const int idx = blockIdx.x * blockDim.x + threadIdx.x;
    if (idx >= 15 * 2048) return;
    const int chunk = idx >> 11;
    const int kp = (idx >> 7) & 15;
    const int c = idx & 127;
    const float* W = (chunk < 8) ? (W_read + chunk * 32 * 128)
                                 : (W_msg + (chunk - 8) * 32 * 128);
    const float x0 = W[(2 * kp) * 128 + c];
    const float x1 = W[(2 * kp + 1) * 128 + c];
    unsigned h, l;
    splitpack(x0, x1, h, l);
    g_Wh[idx] = h;
    g_Wl[idx] = l;
}

// ---------------- edge kernel layout ------------------------------------------
#define PA 20    // split-A stride (conflict-free, proven R3)
#define PW 136   // W stride (proven R3)
#define PS 116   // stage stride (proven R3)
#define PF 36    // fp32 staging stride
#define STRIDE_M 132

// smem u32 offsets
#define O_FPA0 0
#define O_FPA1 4608
#define O_SAH  9216
#define O_SAL  11776
#define O_WH0  14336
#define O_WH1  16512
#define O_WL0  18688
#define O_WL1  20864
#define O_SH   23040
#define O_SL   37888
#define EDGE_U32 52736
#define EDGE_SMEM (EDGE_U32 * 4)

__device__ __forceinline__ void flush_seg(int d, int tx, const float* r, float rl) {
    float* p = g_msg_sum + (size_t)d * D_MSG + tx * 4;
    atomicAdd(p + 0, r[0]);
    atomicAdd(p + 1, r[1]);
    atomicAdd(p + 2, r[2]);
    atomicAdd(p + 3, r[3]);
    if (tx == 0) atomicAdd(&g_cnt[d], rl);
}

// one K=32 chunk of 3-term bf16 mma (proven R3/R4)
__device__ __forceinline__ void mma_k32(const unsigned* __restrict__ Ah,
                                        const unsigned* __restrict__ Al, int strideA,
                                        const unsigned* __restrict__ Wh,
                                        const unsigned* __restrict__ Wl,
                                        int r0, int c0, int gid, int tig,
                                        float acc[2][4][4]) {
#pragma unroll
    for (int half = 0; half < 2; half++) {
        const int kb = half * 8;
        unsigned ah[2][4], al[2][4];
#pragma unroll
        for (int mf = 0; mf < 2; mf++) {
            const int ra = r0 + mf * 16 + gid;
            ah[mf][0] = Ah[ra * strideA + kb + tig];
            ah[mf][1] = Ah[(ra + 8) * strideA + kb + tig];
            ah[mf][2] = Ah[ra * strideA + kb + tig + 4];
            ah[mf][3] = Ah[(ra + 8) * strideA + kb + tig + 4];
            al[mf][0] = Al[ra * strideA + kb + tig];
            al[mf][1] = Al[(ra + 8) * strideA + kb + tig];
            al[mf][2] = Al[ra * strideA + kb + tig + 4];
            al[mf][3] = Al[(ra + 8) * strideA + kb + tig + 4];
        }
#pragma unroll
        for (int nf = 0; nf < 4; nf++) {
            const int col = c0 + nf * 8 + gid;
            unsigned bh[2], bl[2];
            bh[0] = Wh[(kb + tig) * PW + col];
            bh[1] = Wh[(kb + tig + 4) * PW + col];
            bl[0] = Wl[(kb + tig) * PW + col];
            bl[1] = Wl[(kb + tig + 4) * PW + col];
#pragma unroll
            for (int mf = 0; mf < 2; mf++) {
                mma_bf16(acc[mf][nf], ah[mf], bh);
                mma_bf16(acc[mf][nf], ah[mf], bl);
                mma_bf16(acc[mf][nf], al[mf], bh);
            }
        }
    }
}

__global__ __launch_bounds__(512, 1) void edge_kernel(
    const float* __restrict__ node_memory, const float* __restrict__ node_features,
    const float* __restrict__ edge_features, const float* __restrict__ time_encoding,
    const void* __restrict__ node_ids,
    const void* __restrict__ source_ids, const void* __restrict__ edge_ids,
    const void* __restrict__ dest_seg,
    const float* __restrict__ b_read, const float* __restrict__ b_msg,
    float* __restrict__ out) {
    extern __shared__ unsigned su[];
    unsigned* sAh = su + O_SAH;
    unsigned* sAl = su + O_SAL;
    unsigned* bWh[2] = {su + O_WH0, su + O_WH1};
    unsigned* bWl[2] = {su + O_WL0, su + O_WL1};
    unsigned* sSh = su + O_SH;
    unsigned* sSl = su + O_SL;
    __shared__ int s_src[128], s_eid[128], s_dst[128];

    const int tid = threadIdx.x;
    const int lane = tid & 31;
    const int warp = tid >> 5;
    const int gid = lane >> 2;
    const int tig = lane & 3;
    const int r0 = (warp >> 2) * 32;
    const int c0 = (warp & 3) * 32;
    const long long ebase = (long long)blockIdx.x * 128;

    const unsigned* nwid = (const unsigned*)node_ids;
    const int is64 = (nwid[1] == 0u && nwid[3] == 0u);

    if (tid < 128) {
        s_src[tid] = idx_at(source_ids, ebase + tid, is64);
        s_eid[tid] = idx_at(edge_ids, ebase + tid, is64);
        s_dst[tid] = idx_at(dest_seg, ebase + tid, is64);
    }
    __syncthreads();

    const int arow = tid >> 2;          // A fill: row 0..127
    const int aq = tid & 3;             // A fill: quarter (8 floats)
    const int wkp = tid >> 5;           // W fill: kpair 0..15
    const int wc4 = (tid & 31) * 4;     // W fill: col*4

    const unsigned smem_base = (unsigned)__cvta_generic_to_shared(su);
    const unsigned fpA_b[2] = {smem_base + O_FPA0 * 4, smem_base + O_FPA1 * 4};
    const unsigned wh_b[2] = {smem_base + O_WH0 * 4, smem_base + O_WH1 * 4};
    const unsigned wl_b[2] = {smem_base + O_WL0 * 4, smem_base + O_WL1 * 4};

    auto issueA = [&](int kc, int buf) {
        const float* base = (kc < 4)
            ? node_memory + (size_t)s_src[arow] * D_MEM + kc * 32
            : node_features + (size_t)s_src[arow] * D_FEAT + (kc - 4) * 32;
        const unsigned d = fpA_b[buf] + (arow * PF + aq * 8) * 4;
        cp16(d, base + aq * 8);
        cp16(d + 16, base + aq * 8 + 4);
    };
    auto issueW = [&](int gchunk, int buf) {
        const int so = gchunk * 2048 + wkp * 128 + wc4;
        const unsigned doff = (wkp * PW + wc4) * 4;
        cp16(wh_b[buf] + doff, g_Wh + so);
        cp16(wl_b[buf] + doff, g_Wl + so);
    };
    auto splitA = [&](int buf) {
        const float* f = (const float*)(su + (buf ? O_FPA1 : O_FPA0));
        const float4 v0 = *(const float4*)(f + arow * PF + aq * 8);
        const float4 v1 = *(const float4*)(f + arow * PF + aq * 8 + 4);
        unsigned h0, l0, h1, l1, h2, l2, h3, l3;
        splitpack(v0.x, v0.y, h0, l0);
        splitpack(v0.z, v0.w, h1, l1);
        splitpack(v1.x, v1.y, h2, l2);
        splitpack(v1.z, v1.w, h3, l3);
        *(uint4*)(sAh + arow * PA + aq * 4) = make_uint4(h0, h1, h2, h3);
        *(uint4*)(sAl + arow * PA + aq * 4) = make_uint4(l0, l1, l2, l3);
    };

    // prologue: issue chunk 0 (A + W) as group 0
    issueA(0, 0);
    issueW(0, 0);
    CP_COMMIT();

    // prefill stage kpairs [64,112): edge feats (64..95), time (96..111)
    {
        const float4* ef = (const float4*)(edge_features + (size_t)s_eid[arow] * D_EDGE);
#pragma unroll
        for (int j = 0; j < 4; j++) {
            float4 v = ef[aq * 4 + j];
            unsigned h0, l0, h1, l1;
            splitpack(v.x, v.y, h0, l0);
            splitpack(v.z, v.w, h1, l1);
            const int pi = 64 + aq * 8 + 2 * j;
            sSh[arow * PS + pi] = h0;     sSl[arow * PS + pi] = l0;
            sSh[arow * PS + pi + 1] = h1; sSl[arow * PS + pi + 1] = l1;
        }
        const float4* tf = (const float4*)(time_encoding + (ebase + arow) * D_TIME);
#pragma unroll
        for (int j = 0; j < 2; j++) {
            float4 v = tf[aq * 2 + j];
            unsigned h0, l0, h1, l1;
            splitpack(v.x, v.y, h0, l0);
            splitpack(v.z, v.w, h1, l1);
            const int pi = 96 + aq * 4 + 2 * j;
            sSh[arow * PS + pi] = h0;     sSl[arow * PS + pi] = l0;
            sSh[arow * PS + pi + 1] = h1; sSl[arow * PS + pi + 1] = l1;
        }
    }

    float acc[2][4][4];
#pragma unroll
    for (int m = 0; m < 2; m++)
#pragma unroll
        for (int n = 0; n < 4; n++)
#pragma unroll
            for (int c = 0; c < 4; c++) acc[m][n][c] = 0.f;

    // ---- Phase 1: src_read = relu([mem|feat] @ W_read + b), K=256, cp.async pipe ----
    for (int kc = 0; kc < 8; kc++) {
        const int cur = kc & 1, nxt = cur ^ 1;
        if (kc < 7) {
            issueA(kc + 1, nxt);
            issueW(kc + 1, nxt);
        } else {
            issueW(8, nxt);   // phase-2 chunk 0
        }
        CP_COMMIT();
        CP_WAIT1();
        __syncthreads();
        splitA(cur);
        __syncthreads();
        mma_k32(sAh, sAl, PA, bWh[cur], bWl[cur], r0, c0, gid, tig, acc);
    }

    // ---- Phase 1 epilogue: bias+relu -> stage kpairs [0,64) ----
#pragma unroll
    for (int mf = 0; mf < 2; mf++) {
        const int ra = r0 + mf * 16 + gid;
#pragma unroll
        for (int nf = 0; nf < 4; nf++) {
            const int col = c0 + nf * 8 + 2 * tig;
            const int pi = col >> 1;
            const float bb0 = b_read[col], bb1 = b_read[col + 1];
            unsigned h, l;
            float v0 = fmaxf(acc[mf][nf][0] + bb0, 0.f);
            float v1 = fmaxf(acc[mf][nf][1] + bb1, 0.f);
            splitpack(v0, v1, h, l);
            sSh[ra * PS + pi] = h;
            sSl[ra * PS + pi] = l;
            v0 = fmaxf(acc[mf][nf][2] + bb0, 0.f);
            v1 = fmaxf(acc[mf][nf][3] + bb1, 0.f);
            splitpack(v0, v1, h, l);
            sSh[(ra + 8) * PS + pi] = h;
            sSl[(ra + 8) * PS + pi] = l;
        }
    }

    // ---- Phase 2: msgs = relu([src_read|ef|time] @ W_msg + b), K=224 ----
#pragma unroll
    for (int m = 0; m < 2; m++)
#pragma unroll
        for (int n = 0; n < 4; n++)
#pragma unroll
            for (int c = 0; c < 4; c++) acc[m][n][c] = 0.f;

    for (int kc = 0; kc < 7; kc++) {
        const int cur = kc & 1;
        if (kc < 6) {
            issueW(9 + kc, cur ^ 1);
            CP_COMMIT();
            CP_WAIT1();
        } else {
            CP_WAIT0();
        }
        __syncthreads();   // first iter also orders epilogue/prefill writes
        mma_k32(sSh + kc * 16, sSl + kc * 16, PS, bWh[cur], bWl[cur],
                r0, c0, gid, tig, acc);
    }
    __syncthreads();   // all warps done reading stage before msg overwrite

    // ---- Phase 2 epilogue: msgs -> msgbuf fp32 (reuse stage area) ----
    float* msg = (float*)(su + O_SH);   // [128][STRIDE_M]
#pragma unroll
    for (int mf = 0; mf < 2; mf++) {
        const int ra = r0 + mf * 16 + gid;
#pragma unroll
        for (int nf = 0; nf < 4; nf++) {
            const int col = c0 + nf * 8 + 2 * tig;
            const float b0 = b_msg[col], b1 = b_msg[col + 1];
            msg[ra * STRIDE_M + col]           = fmaxf(acc[mf][nf][0] + b0, 0.f);
            msg[ra * STRIDE_M + col + 1]       = fmaxf(acc[mf][nf][1] + b1, 0.f);
            msg[(ra + 8) * STRIDE_M + col]     = fmaxf(acc[mf][nf][2] + b0, 0.f);
            msg[(ra + 8) * STRIDE_M + col + 1] = fmaxf(acc[mf][nf][3] + b1, 0.f);
        }
    }
    __syncthreads();

    // ---- run-coalesced segment-sum atomics (dest_seg globally sorted) ----
    {
        const int tx = lane;
        const int e0 = warp * 8;
        int curd = s_dst[e0];
        float r[4] = {0.f, 0.f, 0.f, 0.f};
        float rl = 0.f;
#pragma unroll
        for (int i = 0; i < 8; i++) {
            const int e = e0 + i;
            const int d = s_dst[e];
            const float4 v = *(const float4*)(msg + e * STRIDE_M + tx * 4);
            if (d != curd) {
                flush_seg(curd, tx, r, rl);
                curd = d;
                r[0] = r[1] = r[2] = r[3] = 0.f;
                rl = 0.f;
            }
            r[0] += v.x; r[1] += v.y; r[2] += v.z; r[3] += v.w;
            rl += 1.f;
        }
        flush_seg(curd, tx, r, rl);
    }

    // ---- node_memory -> out copy slice (rides under compute of other blocks) ----
    {
        const float4* srcm = (const float4*)node_memory;
        float4* dstm = (float4*)out;
        const long long tot = (long long)N_NODES * D_MEM / 4;
        for (long long i = (long long)blockIdx.x * blockDim.x + tid; i < tot;
             i += (long long)gridDim.x * blockDim.x)
            dstm[i] = srcm[i];
    }
}

// ---------------- dest pipeline (fp32, proven; + self-zeroing) ----------------
#define TILE_E 64

__device__ __forceinline__ void mma_chunk(const float* __restrict__ Asub, int strideA,
                                          const float* __restrict__ Ws,
                                          int ty, int tx, float acc[8][4]) {
#pragma unroll
    for (int k = 0; k < 32; k++) {
        const float* arow = Asub + k * strideA + ty * 8;
        float4 a0 = *(const float4*)(arow);
        float4 a1 = *(const float4*)(arow + 4);
        float4 w  = *(const float4*)(Ws + k * 128 + tx * 4);
        float av[8] = {a0.x, a0.y, a0.z, a0.w, a1.x, a1.y, a1.z, a1.w};
#pragma unroll
        for (int i = 0; i < 8; i++) {
            acc[i][0] = fmaf(av[i], w.x, acc[i][0]);
            acc[i][1] = fmaf(av[i], w.y, acc[i][1]);
            acc[i][2] = fmaf(av[i], w.z, acc[i][2]);
            acc[i][3] = fmaf(av[i], w.w, acc[i][3]);
        }
    }
}

__device__ __forceinline__ void load_w(float* Ws, const float* __restrict__ Wsrc, int tid) {
    const float4* s = (const float4*)Wsrc;
    float4* d = (float4*)Ws;
#pragma unroll
    for (int i = 0; i < 4; i++) d[tid + i * 256] = s[tid + i * 256];
}

__device__ __forceinline__ void zero_acc(float acc[8][4]) {
#pragma unroll
    for (int i = 0; i < 8; i++)
#pragma unroll
        for (int c = 0; c < 4; c++) acc[i][c] = 0.f;
}

__global__ __launch_bounds__(256) void dest_kernel(
    const float* __restrict__ node_memory, const float* __restrict__ node_features,
    const void* __restrict__ node_ids,
    const float* __restrict__ W_read, const float* __restrict__ b_read,
    const float* __restrict__ W_agg, const float* __restrict__ b_agg,
    const float* __restrict__ W_upd, const float* __restrict__ b_upd,
    const float* __restrict__ W_write, const float* __restrict__ b_write,
    float* __restrict__ out) {
    extern __shared__ float sm[];
    float* As = sm;             // [32][64]
    float* Ws = sm + 2048;      // [32][128]
    float* CT = sm + 6144;      // [256][68]
    float* DR = sm + 23552;     // [128][68]
    __shared__ int s_nid[TILE_E];

    const int tid = threadIdx.x;
    const int tx = tid & 31;
    const int ty = tid >> 5;
    const int eL = tid & 63;
    const int kq = tid >> 6;
    const int rbase = blockIdx.x * TILE_E;

    const unsigned* nwid = (const unsigned*)node_ids;
    const int is64 = (nwid[1] == 0u && nwid[3] == 0u);

    if (tid < TILE_E) s_nid[tid] = idx_at(node_ids, rbase + tid, is64);

    float acc[8][4];
    zero_acc(acc);

    for (int kc = 0; kc < 8; kc++) {
        __syncthreads();
        {
            const float* row = (kc < 4)
                ? node_memory + (size_t)s_nid[eL] * D_MEM + kc * 32
                : node_features + (size_t)s_nid[eL] * D_FEAT + (kc - 4) * 32;
            float4 v0 = ((const float4*)row)[kq * 2];
            float4 v1 = ((const float4*)row)[kq * 2 + 1];
            int kb = kq * 8;
            As[(kb + 0) * 64 + eL] = v0.x; As[(kb + 1) * 64 + eL] = v0.y;
            As[(kb + 2) * 64 + eL] = v0.z; As[(kb + 3) * 64 + eL] = v0.w;
            As[(kb + 4) * 64 + eL] = v1.x; As[(kb + 5) * 64 + eL] = v1.y;
            As[(kb + 6) * 64 + eL] = v1.z; As[(kb + 7) * 64 + eL] = v1.w;
        }
        load_w(Ws, W_read + kc * 32 * 128, tid);
        __syncthreads();
        mma_chunk(As, 64, Ws, ty, tx, acc);
    }
    {
        float4 bb = *(const float4*)&b_read[tx * 4];
        __syncthreads();
#pragma unroll
        for (int i = 0; i < 8; i++) {
            int e = ty * 8 + i;
#pragma unroll
            for (int c = 0; c < 4; c++) {
                float bv = (c == 0) ? bb.x : (c == 1) ? bb.y : (c == 2) ? bb.z : bb.w;
                float v = fmaxf(acc[i][c] + bv, 0.f);
                CT[(tx * 4 + c) * 68 + e] = v;
                DR[(tx * 4 + c) * 68 + e] = v;
            }
        }
    }
    {
        int dg = rbase + eL;
        float inv = 1.0f / fmaxf(g_cnt[dg], 1.0f);
        const float4* srcp = (const float4*)(g_msg_sum + (size_t)dg * D_MSG + kq * 32);
#pragma unroll
        for (int j4 = 0; j4 < 8; j4++) {
            float4 v = srcp[j4];
            int kk = 128 + kq * 32 + j4 * 4;
            CT[(kk + 0) * 68 + eL] = v.x * inv; CT[(kk + 1) * 68 + eL] = v.y * inv;
            CT[(kk + 2) * 68 + eL] = v.z * inv; CT[(kk + 3) * 68 + eL] = v.w * inv;
        }
    }
    // re-zero the consumed scratch so graph replays stay deterministic
    __syncthreads();
    {
        int dg = rbase + eL;
        float4 z = {0.f, 0.f, 0.f, 0.f};
        float4* p = (float4*)(g_msg_sum + (size_t)dg * D_MSG + kq * 32);
#pragma unroll
        for (int j4 = 0; j4 < 8; j4++) p[j4] = z;
        if (kq == 0) g_cnt[dg] = 0.f;
    }

    zero_acc(acc);
    for (int kc = 0; kc < 8; kc++) {
        __syncthreads();
        load_w(Ws, W_agg + kc * 32 * 128, tid);
        __syncthreads();
        mma_chunk(CT + kc * 32 * 68, 68, Ws, ty, tx, acc);
    }
    __syncthreads();
    {
        float4 ba = *(const float4*)&b_agg[tx * 4];
#pragma unroll
        for (int i = 0; i < 8; i++) {
            int e = ty * 8 + i;
            CT[(tx * 4 + 0) * 68 + e] = fmaxf(acc[i][0] + ba.x, 0.f);
            CT[(tx * 4 + 1) * 68 + e] = fmaxf(acc[i][1] + ba.y, 0.f);
            CT[(tx * 4 + 2) * 68 + e] = fmaxf(acc[i][2] + ba.z, 0.f);
            CT[(tx * 4 + 3) * 68 + e] = fmaxf(acc[i][3] + ba.w, 0.f);
        }
#pragma unroll
        for (int j = 0; j < 32; j++) {
            int row = kq * 32 + j;
            CT[(128 + row) * 68 + eL] = DR[row * 68 + eL];
        }
    }

    zero_acc(acc);
    for (int kc = 0; kc < 8; kc++) {
        __syncthreads();
        load_w(Ws, W_upd + kc * 32 * 128, tid);
        __syncthreads();
        mma_chunk(CT + kc * 32 * 68, 68, Ws, ty, tx, acc);
    }
    __syncthreads();
    {
        float4 bu = *(const float4*)&b_upd[tx * 4];
#pragma unroll
        for (int i = 0; i < 8; i++) {
            int e = ty * 8 + i;
            DR[(tx * 4 + 0) * 68 + e] = fmaxf(acc[i][0] + bu.x, 0.f);
            DR[(tx * 4 + 1) * 68 + e] = fmaxf(acc[i][1] + bu.y, 0.f);
            DR[(tx * 4 + 2) * 68 + e] = fmaxf(acc[i][2] + bu.z, 0.f);
            DR[(tx * 4 + 3) * 68 + e] = fmaxf(acc[i][3] + bu.w, 0.f);
        }
    }

    zero_acc(acc);
    for (int kc = 0; kc < 4; kc++) {
        __syncthreads();
        load_w(Ws, W_write + kc * 32 * 128, tid);
        __syncthreads();
        mma_chunk(DR + kc * 32 * 68, 68, Ws, ty, tx, acc);
    }
    {
        float4 bw = *(const float4*)&b_write[tx * 4];
#pragma unroll
        for (int i = 0; i < 8; i++) {
            int e = ty * 8 + i;
            float4 o;
            o.x = tanhf(acc[i][0] + bw.x);
            o.y = tanhf(acc[i][1] + bw.y);
            o.z = tanhf(acc[i][2] + bw.z);
            o.w = tanhf(acc[i][3] + bw.w);
            *(float4*)(out + (size_t)s_nid[e] * D_MEM + tx * 4) = o;
        }
    }
}

// ---------------- launch ------------------------------------------------------
#define DEST_SMEM ((2048 + 4096 + 256 * 68 + 128 * 68) * 4)

extern "C" void kernel_launch(void* const* d_in, const int* in_sizes, int n_in,
                              void* d_out, int out_size) {
    const float* node_memory   = (const float*)d_in[0];
    const float* node_features = (const float*)d_in[1];
    const float* edge_features = (const float*)d_in[2];
    const float* time_encoding = (const float*)d_in[3];
    const void*  node_ids      = d_in[4];
    const void*  source_ids    = d_in[5];
    const void*  edge_ids      = d_in[6];
    const void*  dest_seg      = d_in[7];
    const float* W_read  = (const float*)d_in[8];
    const float* b_read  = (const float*)d_in[9];
    const float* W_msg   = (const float*)d_in[10];
    const float* b_msg   = (const float*)d_in[11];
    const float* W_agg   = (const float*)d_in[12];
    const float* b_agg   = (const float*)d_in[13];
    const float* W_upd   = (const float*)d_in[14];
    const float* b_upd   = (const float*)d_in[15];
    const float* W_write = (const float*)d_in[16];
    const float* b_write = (const float*)d_in[17];
    float* out = (float*)d_out;

    cudaFuncSetAttribute(edge_kernel, cudaFuncAttributeMaxDynamicSharedMemorySize, EDGE_SMEM);
    cudaFuncSetAttribute(dest_kernel, cudaFuncAttributeMaxDynamicSharedMemorySize, DEST_SMEM);

    prep_kernel<<<120, 256>>>(W_read, W_msg);

    edge_kernel<<<N_EDGE / 128, 512, EDGE_SMEM>>>(
        node_memory, node_features, edge_features, time_encoding, node_ids,
        source_ids, edge_ids, dest_seg, b_read, b_msg, out);

    dest_kernel<<<N_DEST / TILE_E, 256, DEST_SMEM>>>(
        node_memory, node_features, node_ids,
        W_read, b_read, W_agg, b_agg, W_upd, b_upd, W_write, b_write, out);
}

// round 8
// speedup vs baseline: 1.2490x; 1.0996x over previous
#include <cuda_runtime.h>
#include <cuda_bf16.h>
#include <math.h>

#define N_NODES 200000
#define N_DEST  8192
#define N_EDGE  262144
#define D_MEM   128
#define D_FEAT  128
#define D_EDGE  64
#define D_TIME  32
#define D_MSG   128

// ---------------- scratch (device globals: allocation-free) ------------------
__device__ float g_msg_sum[N_DEST * D_MSG];   // zero-init; dest_kernel re-zeroes
__device__ float g_cnt[N_DEST];
__device__ unsigned g_Wh[15 * 2048];          // pre-split W_read(8)+W_msg(7) chunks
__device__ unsigned g_Wl[15 * 2048];          // packed bf16x2 hi/lo, [chunk][kp][128]

__device__ __forceinline__ int idx_at(const void* p, long long i, int is64) {
    return is64 ? (int)((const long long*)p)[i] : ((const int*)p)[i];
}

// ---------------- bf16 split-pack (numerics proven R3: rel_err 3.8e-8) --------
__device__ __forceinline__ void splitpack(float x0, float x1, unsigned& hi, unsigned& lo) {
    unsigned h;
    asm("cvt.rn.bf16x2.f32 %0, %1, %2;" : "=r"(h) : "f"(x1), "f"(x0));
    float h0 = __uint_as_float(h << 16);
    float h1 = __uint_as_float(h & 0xFFFF0000u);
    float r0 = x0 - h0;
    float r1 = x1 - h1;
    unsigned l;
    asm("cvt.rn.bf16x2.f32 %0, %1, %2;" : "=r"(l) : "f"(r1), "f"(r0));
    hi = h;
    lo = l;
}

__device__ __forceinline__ void mma_bf16(float* c, const unsigned* a, const unsigned* b) {
    asm volatile(
        "mma.sync.aligned.m16n8k16.row.col.f32.bf16.bf16.f32 "
        "{%0,%1,%2,%3},{%4,%5,%6,%7},{%8,%9},{%0,%1,%2,%3};"
        : "+f"(c[0]), "+f"(c[1]), "+f"(c[2]), "+f"(c[3])
        : "r"(a[0]), "r"(a[1]), "r"(a[2]), "r"(a[3]), "r"(b[0]), "r"(b[1]));
}

// ---------------- prep: pre-split weights into bf16x2 hi/lo -------------------
__global__ void prep_kernel(const float* __restrict__ W_read,
                            const float* __restrict__ W_msg) {
    const int idx = blockIdx.x * blockDim.x + threadIdx.x;
    if (idx >= 15 * 2048) return;
    const int chunk = idx >> 11;
    const int kp = (idx >> 7) & 15;
    const int c = idx & 127;
    const float* W = (chunk < 8) ? (W_read + chunk * 32 * 128)
                                 : (W_msg + (chunk - 8) * 32 * 128);
    const float x0 = W[(2 * kp) * 128 + c];
    const float x1 = W[(2 * kp + 1) * 128 + c];
    unsigned h, l;
    splitpack(x0, x1, h, l);
    g_Wh[idx] = h;
    g_Wl[idx] = l;
}

// ---------------- edge kernel: 64-edge tile, 256 thr, 2 CTAs/SM ---------------
#define PA 20    // split-A stride (conflict-free, proven R3)
#define PW 136   // W stride (proven R3)
#define PS 116   // stage stride (proven R3)
#define STRIDE_M 132

// smem u32 offsets (64-row tiles)
#define O_AH 0
#define O_AL 1280
#define O_WH 2560
#define O_WL 4736
#define O_SH 6912
#define O_SL 14336
#define EDGE_U32 21760
#define EDGE_SMEM (EDGE_U32 * 4)   // 87040 B -> 2 CTAs/SM

__device__ __forceinline__ void flush_seg(int d, int tx, const float* r, float rl) {
    float* p = g_msg_sum + (size_t)d * D_MSG + tx * 4;
    atomicAdd(p + 0, r[0]);
    atomicAdd(p + 1, r[1]);
    atomicAdd(p + 2, r[2]);
    atomicAdd(p + 3, r[3]);
    if (tx == 0) atomicAdd(&g_cnt[d], rl);
}

// one K=32 chunk of 3-term bf16 mma (proven R3)
__device__ __forceinline__ void mma_k32(const unsigned* __restrict__ Ah,
                                        const unsigned* __restrict__ Al, int strideA,
                                        const unsigned* __restrict__ Wh,
                                        const unsigned* __restrict__ Wl,
                                        int r0, int c0, int gid, int tig,
                                        float acc[2][4][4]) {
#pragma unroll
    for (int half = 0; half < 2; half++) {
        const int kb = half * 8;
        unsigned ah[2][4], al[2][4];
#pragma unroll
        for (int mf = 0; mf < 2; mf++) {
            const int ra = r0 + mf * 16 + gid;
            ah[mf][0] = Ah[ra * strideA + kb + tig];
            ah[mf][1] = Ah[(ra + 8) * strideA + kb + tig];
            ah[mf][2] = Ah[ra * strideA + kb + tig + 4];
            ah[mf][3] = Ah[(ra + 8) * strideA + kb + tig + 4];
            al[mf][0] = Al[ra * strideA + kb + tig];
            al[mf][1] = Al[(ra + 8) * strideA + kb + tig];
            al[mf][2] = Al[ra * strideA + kb + tig + 4];
            al[mf][3] = Al[(ra + 8) * strideA + kb + tig + 4];
        }
#pragma unroll
        for (int nf = 0; nf < 4; nf++) {
            const int col = c0 + nf * 8 + gid;
            unsigned bh[2], bl[2];
            bh[0] = Wh[(kb + tig) * PW + col];
            bh[1] = Wh[(kb + tig + 4) * PW + col];
            bl[0] = Wl[(kb + tig) * PW + col];
            bl[1] = Wl[(kb + tig + 4) * PW + col];
#pragma unroll
            for (int mf = 0; mf < 2; mf++) {
                mma_bf16(acc[mf][nf], ah[mf], bh);
                mma_bf16(acc[mf][nf], ah[mf], bl);
                mma_bf16(acc[mf][nf], al[mf], bh);
            }
        }
    }
}

__global__ __launch_bounds__(256, 2) void edge_kernel(
    const float* __restrict__ node_memory, const float* __restrict__ node_features,
    const float* __restrict__ edge_features, const float* __restrict__ time_encoding,
    const void* __restrict__ node_ids,
    const void* __restrict__ source_ids, const void* __restrict__ edge_ids,
    const void* __restrict__ dest_seg,
    const float* __restrict__ b_read, const float* __restrict__ b_msg,
    float* __restrict__ out) {
    extern __shared__ unsigned su[];
    unsigned* sAh = su + O_AH;
    unsigned* sAl = su + O_AL;
    unsigned* sWh = su + O_WH;
    unsigned* sWl = su + O_WL;
    unsigned* sSh = su + O_SH;
    unsigned* sSl = su + O_SL;
    __shared__ int s_src[64], s_eid[64], s_dst[64];

    const int tid = threadIdx.x;
    const int lane = tid & 31;
    const int warp = tid >> 5;
    const int gid = lane >> 2;
    const int tig = lane & 3;
    const int r0 = (warp >> 2) * 32;   // 0 or 32
    const int c0 = (warp & 3) * 32;    // 0..96
    const long long ebase = (long long)blockIdx.x * 64;

    const unsigned* nwid = (const unsigned*)node_ids;
    const int is64 = (nwid[1] == 0u && nwid[3] == 0u);

    if (tid < 64) {
        s_src[tid] = idx_at(source_ids, ebase + tid, is64);
        s_eid[tid] = idx_at(edge_ids, ebase + tid, is64);
        s_dst[tid] = idx_at(dest_seg, ebase + tid, is64);
    }
    __syncthreads();

    const int arow = tid >> 2;    // fill row 0..63
    const int aq = tid & 3;       // fill quarter (8 floats)
    const int wkp = tid >> 4;     // W fill kpair 0..15
    const int wc8 = (tid & 15) * 8;

    // ---- prefill stage kpairs [64,112): edge feats (64..95), time (96..111) ----
    {
        const float4* ef = (const float4*)(edge_features + (size_t)s_eid[arow] * D_EDGE);
#pragma unroll
        for (int j = 0; j < 4; j++) {
            float4 v = ef[aq * 4 + j];
            unsigned h0, l0, h1, l1;
            splitpack(v.x, v.y, h0, l0);
            splitpack(v.z, v.w, h1, l1);
            const int pi = 64 + aq * 8 + 2 * j;
            sSh[arow * PS + pi] = h0;     sSl[arow * PS + pi] = l0;
            sSh[arow * PS + pi + 1] = h1; sSl[arow * PS + pi + 1] = l1;
        }
        const float4* tf = (const float4*)(time_encoding + (ebase + arow) * D_TIME);
#pragma unroll
        for (int j = 0; j < 2; j++) {
            float4 v = tf[aq * 2 + j];
            unsigned h0, l0, h1, l1;
            splitpack(v.x, v.y, h0, l0);
            splitpack(v.z, v.w, h1, l1);
            const int pi = 96 + aq * 4 + 2 * j;
            sSh[arow * PS + pi] = h0;     sSl[arow * PS + pi] = l0;
            sSh[arow * PS + pi + 1] = h1; sSl[arow * PS + pi + 1] = l1;
        }
    }

    float acc[2][4][4];
#pragma unroll
    for (int m = 0; m < 2; m++)
#pragma unroll
        for (int n = 0; n < 4; n++)
#pragma unroll
            for (int c = 0; c < 4; c++) acc[m][n][c] = 0.f;

    // ---- Phase 1: src_read = relu([mem|feat] @ W_read + b), K=256 ----
    for (int kc = 0; kc < 8; kc++) {
        __syncthreads();
        {   // gather + split A chunk [64 rows][32 k]
            const float* base = (kc < 4)
                ? node_memory + (size_t)s_src[arow] * D_MEM + kc * 32
                : node_features + (size_t)s_src[arow] * D_FEAT + (kc - 4) * 32;
            const float4* b4 = (const float4*)base;
            float4 va = b4[aq * 2];
            float4 vb = b4[aq * 2 + 1];
            unsigned h0, l0, h1, l1, h2, l2, h3, l3;
            splitpack(va.x, va.y, h0, l0);
            splitpack(va.z, va.w, h1, l1);
            splitpack(vb.x, vb.y, h2, l2);
            splitpack(vb.z, vb.w, h3, l3);
            *(uint4*)(sAh + arow * PA + aq * 4) = make_uint4(h0, h1, h2, h3);
            *(uint4*)(sAl + arow * PA + aq * 4) = make_uint4(l0, l1, l2, l3);
        }
        {   // copy pre-split W chunk (L2-resident): 8 u32 per thread per array
            const unsigned* gh = g_Wh + kc * 2048 + wkp * 128 + wc8;
            const unsigned* gl = g_Wl + kc * 2048 + wkp * 128 + wc8;
            unsigned* dh = sWh + wkp * PW + wc8;
            unsigned* dl = sWl + wkp * PW + wc8;
            *(uint4*)dh = *(const uint4*)gh;
            *(uint4*)(dh + 4) = *(const uint4*)(gh + 4);
            *(uint4*)dl = *(const uint4*)gl;
            *(uint4*)(dl + 4) = *(const uint4*)(gl + 4);
        }
        __syncthreads();
        mma_k32(sAh, sAl, PA, sWh, sWl, r0, c0, gid, tig, acc);
    }

    // ---- Phase 1 epilogue: bias+relu -> stage kpairs [0,64) ----
    __syncthreads();
#pragma unroll
    for (int mf = 0; mf < 2; mf++) {
        const int ra = r0 + mf * 16 + gid;
#pragma unroll
        for (int nf = 0; nf < 4; nf++) {
            const int col = c0 + nf * 8 + 2 * tig;
            const int pi = col >> 1;
            const float bb0 = b_read[col], bb1 = b_read[col + 1];
            unsigned h, l;
            float v0 = fmaxf(acc[mf][nf][0] + bb0, 0.f);
            float v1 = fmaxf(acc[mf][nf][1] + bb1, 0.f);
            splitpack(v0, v1, h, l);
            sSh[ra * PS + pi] = h;
            sSl[ra * PS + pi] = l;
            v0 = fmaxf(acc[mf][nf][2] + bb0, 0.f);
            v1 = fmaxf(acc[mf][nf][3] + bb1, 0.f);
            splitpack(v0, v1, h, l);
            sSh[(ra + 8) * PS + pi] = h;
            sSl[(ra + 8) * PS + pi] = l;
        }
    }

    // ---- Phase 2: msgs = relu([src_read|ef|time] @ W_msg + b), K=224 ----
#pragma unroll
    for (int m = 0; m < 2; m++)
#pragma unroll
        for (int n = 0; n < 4; n++)
#pragma unroll
            for (int c = 0; c < 4; c++) acc[m][n][c] = 0.f;

    for (int kc = 0; kc < 7; kc++) {
        __syncthreads();
        {   // copy pre-split W_msg chunk
            const unsigned* gh = g_Wh + (8 + kc) * 2048 + wkp * 128 + wc8;
            const unsigned* gl = g_Wl + (8 + kc) * 2048 + wkp * 128 + wc8;
            unsigned* dh = sWh + wkp * PW + wc8;
            unsigned* dl = sWl + wkp * PW + wc8;
            *(uint4*)dh = *(const uint4*)gh;
            *(uint4*)(dh + 4) = *(const uint4*)(gh + 4);
            *(uint4*)dl = *(const uint4*)gl;
            *(uint4*)(dl + 4) = *(const uint4*)(gl + 4);
        }
        __syncthreads();
        mma_k32(sSh + kc * 16, sSl + kc * 16, PS, sWh, sWl, r0, c0, gid, tig, acc);
    }
    __syncthreads();   // all warps done reading stage before msg overwrite

    // ---- Phase 2 epilogue: msgs -> msgbuf fp32 (reuse stage area) ----
    float* msg = (float*)(su + O_SH);   // [64][STRIDE_M]
#pragma unroll
    for (int mf = 0; mf < 2; mf++) {
        const int ra = r0 + mf * 16 + gid;
#pragma unroll
        for (int nf = 0; nf < 4; nf++) {
            const int col = c0 + nf * 8 + 2 * tig;
            const float b0 = b_msg[col], b1 = b_msg[col + 1];
            msg[ra * STRIDE_M + col]           = fmaxf(acc[mf][nf][0] + b0, 0.f);
            msg[ra * STRIDE_M + col + 1]       = fmaxf(acc[mf][nf][1] + b1, 0.f);
            msg[(ra + 8) * STRIDE_M + col]     = fmaxf(acc[mf][nf][2] + b0, 0.f);
            msg[(ra + 8) * STRIDE_M + col + 1] = fmaxf(acc[mf][nf][3] + b1, 0.f);
        }
    }
    __syncthreads();

    // ---- run-coalesced segment-sum atomics (dest_seg globally sorted) ----
    {
        const int tx = lane;          // 4 cols per lane
        const int e0 = warp * 8;      // 8 warps x 8 edges
        int curd = s_dst[e0];
        float r[4] = {0.f, 0.f, 0.f, 0.f};
        float rl = 0.f;
#pragma unroll
        for (int i = 0; i < 8; i++) {
            const int e = e0 + i;
            const int d = s_dst[e];
            const float4 v = *(const float4*)(msg + e * STRIDE_M + tx * 4);
            if (d != curd) {
                flush_seg(curd, tx, r, rl);
                curd = d;
                r[0] = r[1] = r[2] = r[3] = 0.f;
                rl = 0.f;
            }
            r[0] += v.x; r[1] += v.y; r[2] += v.z; r[3] += v.w;
            rl += 1.f;
        }
        flush_seg(curd, tx, r, rl);
    }

    // ---- node_memory -> out copy slice (rides under compute) ----
    {
        const float4* srcm = (const float4*)node_memory;
        float4* dstm = (float4*)out;
        const long long tot = (long long)N_NODES * D_MEM / 4;
        for (long long i = (long long)blockIdx.x * blockDim.x + tid; i < tot;
             i += (long long)gridDim.x * blockDim.x)
            dstm[i] = srcm[i];
    }
}

// ---------------- dest pipeline (fp32, proven; + self-zeroing) ----------------
#define TILE_E 64

__device__ __forceinline__ void mma_chunk(const float* __restrict__ Asub, int strideA,
                                          const float* __restrict__ Ws,
                                          int ty, int tx, float acc[8][4]) {
#pragma unroll
    for (int k = 0; k < 32; k++) {
        const float* arow = Asub + k * strideA + ty * 8;
        float4 a0 = *(const float4*)(arow);
        float4 a1 = *(const float4*)(arow + 4);
        float4 w  = *(const float4*)(Ws + k * 128 + tx * 4);
        float av[8] = {a0.x, a0.y, a0.z, a0.w, a1.x, a1.y, a1.z, a1.w};
#pragma unroll
        for (int i = 0; i < 8; i++) {
            acc[i][0] = fmaf(av[i], w.x, acc[i][0]);
            acc[i][1] = fmaf(av[i], w.y, acc[i][1]);
            acc[i][2] = fmaf(av[i], w.z, acc[i][2]);
            acc[i][3] = fmaf(av[i], w.w, acc[i][3]);
        }
    }
}

__device__ __forceinline__ void load_w(float* Ws, const float* __restrict__ Wsrc, int tid) {
    const float4* s = (const float4*)Wsrc;
    float4* d = (float4*)Ws;
#pragma unroll
    for (int i = 0; i < 4; i++) d[tid + i * 256] = s[tid + i * 256];
}

__device__ __forceinline__ void zero_acc(float acc[8][4]) {
#pragma unroll
    for (int i = 0; i < 8; i++)
#pragma unroll
        for (int c = 0; c < 4; c++) acc[i][c] = 0.f;
}

__global__ __launch_bounds__(256) void dest_kernel(
    const float* __restrict__ node_memory, const float* __restrict__ node_features,
    const void* __restrict__ node_ids,
    const float* __restrict__ W_read, const float* __restrict__ b_read,
    const float* __restrict__ W_agg, const float* __restrict__ b_agg,
    const float* __restrict__ W_upd, const float* __restrict__ b_upd,
    const float* __restrict__ W_write, const float* __restrict__ b_write,
    float* __restrict__ out) {
    extern __shared__ float sm[];
    float* As = sm;             // [32][64]
    float* Ws = sm + 2048;      // [32][128]
    float* CT = sm + 6144;      // [256][68]
    float* DR = sm + 23552;     // [128][68]
    __shared__ int s_nid[TILE_E];

    const int tid = threadIdx.x;
    const int tx = tid & 31;
    const int ty = tid >> 5;
    const int eL = tid & 63;
    const int kq = tid >> 6;
    const int rbase = blockIdx.x * TILE_E;

    const unsigned* nwid = (const unsigned*)node_ids;
    const int is64 = (nwid[1] == 0u && nwid[3] == 0u);

    if (tid < TILE_E) s_nid[tid] = idx_at(node_ids, rbase + tid, is64);

    float acc[8][4];
    zero_acc(acc);

    for (int kc = 0; kc < 8; kc++) {
        __syncthreads();
        {
            const float* row = (kc < 4)
                ? node_memory + (size_t)s_nid[eL] * D_MEM + kc * 32
                : node_features + (size_t)s_nid[eL] * D_FEAT + (kc - 4) * 32;
            float4 v0 = ((const float4*)row)[kq * 2];
            float4 v1 = ((const float4*)row)[kq * 2 + 1];
            int kb = kq * 8;
            As[(kb + 0) * 64 + eL] = v0.x; As[(kb + 1) * 64 + eL] = v0.y;
            As[(kb + 2) * 64 + eL] = v0.z; As[(kb + 3) * 64 + eL] = v0.w;
            As[(kb + 4) * 64 + eL] = v1.x; As[(kb + 5) * 64 + eL] = v1.y;
            As[(kb + 6) * 64 + eL] = v1.z; As[(kb + 7) * 64 + eL] = v1.w;
        }
        load_w(Ws, W_read + kc * 32 * 128, tid);
        __syncthreads();
        mma_chunk(As, 64, Ws, ty, tx, acc);
    }
    {
        float4 bb = *(const float4*)&b_read[tx * 4];
        __syncthreads();
#pragma unroll
        for (int i = 0; i < 8; i++) {
            int e = ty * 8 + i;
#pragma unroll
            for (int c = 0; c < 4; c++) {
                float bv = (c == 0) ? bb.x : (c == 1) ? bb.y : (c == 2) ? bb.z : bb.w;
                float v = fmaxf(acc[i][c] + bv, 0.f);
                CT[(tx * 4 + c) * 68 + e] = v;
                DR[(tx * 4 + c) * 68 + e] = v;
            }
        }
    }
    {
        int dg = rbase + eL;
        float inv = 1.0f / fmaxf(g_cnt[dg], 1.0f);
        const float4* srcp = (const float4*)(g_msg_sum + (size_t)dg * D_MSG + kq * 32);
#pragma unroll
        for (int j4 = 0; j4 < 8; j4++) {
            float4 v = srcp[j4];
            int kk = 128 + kq * 32 + j4 * 4;
            CT[(kk + 0) * 68 + eL] = v.x * inv; CT[(kk + 1) * 68 + eL] = v.y * inv;
            CT[(kk + 2) * 68 + eL] = v.z * inv; CT[(kk + 3) * 68 + eL] = v.w * inv;
        }
    }
    __syncthreads();
    {
        int dg = rbase + eL;
        float4 z = {0.f, 0.f, 0.f, 0.f};
        float4* p = (float4*)(g_msg_sum + (size_t)dg * D_MSG + kq * 32);
#pragma unroll
        for (int j4 = 0; j4 < 8; j4++) p[j4] = z;
        if (kq == 0) g_cnt[dg] = 0.f;
    }

    zero_acc(acc);
    for (int kc = 0; kc < 8; kc++) {
        __syncthreads();
        load_w(Ws, W_agg + kc * 32 * 128, tid);
        __syncthreads();
        mma_chunk(CT + kc * 32 * 68, 68, Ws, ty, tx, acc);
    }
    __syncthreads();
    {
        float4 ba = *(const float4*)&b_agg[tx * 4];
#pragma unroll
        for (int i = 0; i < 8; i++) {
            int e = ty * 8 + i;
            CT[(tx * 4 + 0) * 68 + e] = fmaxf(acc[i][0] + ba.x, 0.f);
            CT[(tx * 4 + 1) * 68 + e] = fmaxf(acc[i][1] + ba.y, 0.f);
            CT[(tx * 4 + 2) * 68 + e] = fmaxf(acc[i][2] + ba.z, 0.f);
            CT[(tx * 4 + 3) * 68 + e] = fmaxf(acc[i][3] + ba.w, 0.f);
        }
#pragma unroll
        for (int j = 0; j < 32; j++) {
            int row = kq * 32 + j;
            CT[(128 + row) * 68 + eL] = DR[row * 68 + eL];
        }
    }

    zero_acc(acc);
    for (int kc = 0; kc < 8; kc++) {
        __syncthreads();
        load_w(Ws, W_upd + kc * 32 * 128, tid);
        __syncthreads();
        mma_chunk(CT + kc * 32 * 68, 68, Ws, ty, tx, acc);
    }
    __syncthreads();
    {
        float4 bu = *(const float4*)&b_upd[tx * 4];
#pragma unroll
        for (int i = 0; i < 8; i++) {
            int e = ty * 8 + i;
            DR[(tx * 4 + 0) * 68 + e] = fmaxf(acc[i][0] + bu.x, 0.f);
            DR[(tx * 4 + 1) * 68 + e] = fmaxf(acc[i][1] + bu.y, 0.f);
            DR[(tx * 4 + 2) * 68 + e] = fmaxf(acc[i][2] + bu.z, 0.f);
            DR[(tx * 4 + 3) * 68 + e] = fmaxf(acc[i][3] + bu.w, 0.f);
        }
    }

    zero_acc(acc);
    for (int kc = 0; kc < 4; kc++) {
        __syncthreads();
        load_w(Ws, W_write + kc * 32 * 128, tid);
        __syncthreads();
        mma_chunk(DR + kc * 32 * 68, 68, Ws, ty, tx, acc);
    }
    {
        float4 bw = *(const float4*)&b_write[tx * 4];
#pragma unroll
        for (int i = 0; i < 8; i++) {
            int e = ty * 8 + i;
            float4 o;
            o.x = tanhf(acc[i][0] + bw.x);
            o.y = tanhf(acc[i][1] + bw.y);
            o.z = tanhf(acc[i][2] + bw.z);
            o.w = tanhf(acc[i][3] + bw.w);
            *(float4*)(out + (size_t)s_nid[e] * D_MEM + tx * 4) = o;
        }
    }
}

// ---------------- launch ------------------------------------------------------
#define DEST_SMEM ((2048 + 4096 + 256 * 68 + 128 * 68) * 4)

extern "C" void kernel_launch(void* const* d_in, const int* in_sizes, int n_in,
                              void* d_out, int out_size) {
    const float* node_memory   = (const float*)d_in[0];
    const float* node_features = (const float*)d_in[1];
    const float* edge_features = (const float*)d_in[2];
    const float* time_encoding = (const float*)d_in[3];
    const void*  node_ids      = d_in[4];
    const void*  source_ids    = d_in[5];
    const void*  edge_ids      = d_in[6];
    const void*  dest_seg      = d_in[7];
    const float* W_read  = (const float*)d_in[8];
    const float* b_read  = (const float*)d_in[9];
    const float* W_msg   = (const float*)d_in[10];
    const float* b_msg   = (const float*)d_in[11];
    const float* W_agg   = (const float*)d_in[12];
    const float* b_agg   = (const float*)d_in[13];
    const float* W_upd   = (const float*)d_in[14];
    const float* b_upd   = (const float*)d_in[15];
    const float* W_write = (const float*)d_in[16];
    const float* b_write = (const float*)d_in[17];
    float* out = (float*)d_out;

    cudaFuncSetAttribute(edge_kernel, cudaFuncAttributeMaxDynamicSharedMemorySize, EDGE_SMEM);
    cudaFuncSetAttribute(dest_kernel, cudaFuncAttributeMaxDynamicSharedMemorySize, DEST_SMEM);

    prep_kernel<<<120, 256>>>(W_read, W_msg);

    edge_kernel<<<N_EDGE / 64, 256, EDGE_SMEM>>>(
        node_memory, node_features, edge_features, time_encoding, node_ids,
        source_ids, edge_ids, dest_seg, b_read, b_msg, out);

    dest_kernel<<<N_DEST / TILE_E, 256, DEST_SMEM>>>(
        node_memory, node_features, node_ids,
        W_read, b_read, W_agg, b_agg, W_upd, b_upd, W_write, b_write, out);
}

// round 9
// speedup vs baseline: 2.0506x; 1.6417x over previous
#include <cuda_runtime.h>
#include <cuda_fp16.h>
#include <math.h>

#define N_NODES 200000
#define N_DEST  8192
#define N_EDGE  262144
#define D_MEM   128
#define D_FEAT  128
#define D_EDGE  64
#define D_TIME  32
#define D_MSG   128

// ---------------- scratch (device globals: allocation-free) ------------------
__device__ float g_msg_sum[N_DEST * D_MSG];   // zero-init; dest_kernel re-zeroes
__device__ float g_cnt[N_DEST];
__device__ unsigned g_Wf[15 * 2048];          // pre-packed fp16x2 W chunks [chunk][kp][128]

__device__ __forceinline__ int idx_at(const void* p, long long i, int is64) {
    return is64 ? (int)((const long long*)p)[i] : ((const int*)p)[i];
}

// ---------------- fp16 pack helpers -------------------------------------------
__device__ __forceinline__ unsigned pack_f16(float x0, float x1) {
    unsigned r;
    asm("cvt.rn.f16x2.f32 %0, %1, %2;" : "=r"(r) : "f"(x1), "f"(x0));
    return r;
}

__device__ __forceinline__ void mma_f16(float* c, const unsigned* a, const unsigned* b) {
    asm volatile(
        "mma.sync.aligned.m16n8k16.row.col.f32.f16.f16.f32 "
        "{%0,%1,%2,%3},{%4,%5,%6,%7},{%8,%9},{%0,%1,%2,%3};"
        : "+f"(c[0]), "+f"(c[1]), "+f"(c[2]), "+f"(c[3])
        : "r"(a[0]), "r"(a[1]), "r"(a[2]), "r"(a[3]), "r"(b[0]), "r"(b[1]));
}

// ---------------- prep: pre-pack weights into fp16x2 --------------------------
__global__ void prep_kernel(const float* __restrict__ W_read,
                            const float* __restrict__ W_msg) {
    const int idx = blockIdx.x * blockDim.x + threadIdx.x;
    if (idx >= 15 * 2048) return;
    const int chunk = idx >> 11;
    const int kp = (idx >> 7) & 15;
    const int c = idx & 127;
    const float* W = (chunk < 8) ? (W_read + chunk * 32 * 128)
                                 : (W_msg + (chunk - 8) * 32 * 128);
    g_Wf[idx] = pack_f16(W[(2 * kp) * 128 + c], W[(2 * kp + 1) * 128 + c]);
}

// ---------------- edge kernel: 64-edge tile, 256 thr, 1-term fp16 -------------
#define PA 20    // A stride (conflict-free, proven)
#define PW 136   // W stride (proven)
#define PS 116   // stage stride (proven)
#define STRIDE_M 132

// smem u32 offsets
#define O_AH 0                      // A:     64 x PA  = 1280
#define O_WH 1280                   // W:     16 x PW  = 2176
#define O_SH 3456                   // stage: 64 x PS  = 7424 | msg: 64 x 132 = 8448
#define EDGE_U32 (3456 + 8448)
#define EDGE_SMEM (EDGE_U32 * 4)    // 47616 B

__device__ __forceinline__ void flush_seg(int d, int tx, const float* r, float rl) {
    float* p = g_msg_sum + (size_t)d * D_MSG + tx * 4;
    atomicAdd(p + 0, r[0]);
    atomicAdd(p + 1, r[1]);
    atomicAdd(p + 2, r[2]);
    atomicAdd(p + 3, r[3]);
    if (tx == 0) atomicAdd(&g_cnt[d], rl);
}

// one K=32 chunk of 1-term fp16 mma
__device__ __forceinline__ void mma_k32(const unsigned* __restrict__ Ah, int strideA,
                                        const unsigned* __restrict__ Wh,
                                        int r0, int c0, int gid, int tig,
                                        float acc[2][4][4]) {
#pragma unroll
    for (int half = 0; half < 2; half++) {
        const int kb = half * 8;
        unsigned ah[2][4];
#pragma unroll
        for (int mf = 0; mf < 2; mf++) {
            const int ra = r0 + mf * 16 + gid;
            ah[mf][0] = Ah[ra * strideA + kb + tig];
            ah[mf][1] = Ah[(ra + 8) * strideA + kb + tig];
            ah[mf][2] = Ah[ra * strideA + kb + tig + 4];
            ah[mf][3] = Ah[(ra + 8) * strideA + kb + tig + 4];
        }
#pragma unroll
        for (int nf = 0; nf < 4; nf++) {
            const int col = c0 + nf * 8 + gid;
            unsigned bh[2];
            bh[0] = Wh[(kb + tig) * PW + col];
            bh[1] = Wh[(kb + tig + 4) * PW + col];
#pragma unroll
            for (int mf = 0; mf < 2; mf++) mma_f16(acc[mf][nf], ah[mf], bh);
        }
    }
}

__global__ __launch_bounds__(256, 3) void edge_kernel(
    const float* __restrict__ node_memory, const float* __restrict__ node_features,
    const float* __restrict__ edge_features, const float* __restrict__ time_encoding,
    const void* __restrict__ node_ids,
    const void* __restrict__ source_ids, const void* __restrict__ edge_ids,
    const void* __restrict__ dest_seg,
    const float* __restrict__ b_read, const float* __restrict__ b_msg,
    float* __restrict__ out) {
    extern __shared__ unsigned su[];
    unsigned* sAh = su + O_AH;
    unsigned* sWh = su + O_WH;
    unsigned* sSh = su + O_SH;
    __shared__ int s_src[64], s_eid[64], s_dst[64];

    const int tid = threadIdx.x;
    const int lane = tid & 31;
    const int warp = tid >> 5;
    const int gid = lane >> 2;
    const int tig = lane & 3;
    const int r0 = (warp >> 2) * 32;   // 0 or 32
    const int c0 = (warp & 3) * 32;    // 0..96
    const long long ebase = (long long)blockIdx.x * 64;

    const unsigned* nwid = (const unsigned*)node_ids;
    const int is64 = (nwid[1] == 0u && nwid[3] == 0u);

    if (tid < 64) {
        s_src[tid] = idx_at(source_ids, ebase + tid, is64);
        s_eid[tid] = idx_at(edge_ids, ebase + tid, is64);
        s_dst[tid] = idx_at(dest_seg, ebase + tid, is64);
    }
    __syncthreads();

    const int arow = tid >> 2;    // fill row 0..63
    const int aq = tid & 3;       // fill quarter (8 floats)
    const int wkp = tid >> 4;     // W fill kpair 0..15
    const int wc8 = (tid & 15) * 8;

    // ---- prefill stage kpairs [64,112): edge feats (64..95), time (96..111) ----
    {
        const float4* ef = (const float4*)(edge_features + (size_t)s_eid[arow] * D_EDGE);
#pragma unroll
        for (int j = 0; j < 4; j++) {
            float4 v = ef[aq * 4 + j];
            const int pi = 64 + aq * 8 + 2 * j;
            sSh[arow * PS + pi] = pack_f16(v.x, v.y);
            sSh[arow * PS + pi + 1] = pack_f16(v.z, v.w);
        }
        const float4* tf = (const float4*)(time_encoding + (ebase + arow) * D_TIME);
#pragma unroll
        for (int j = 0; j < 2; j++) {
            float4 v = tf[aq * 2 + j];
            const int pi = 96 + aq * 4 + 2 * j;
            sSh[arow * PS + pi] = pack_f16(v.x, v.y);
            sSh[arow * PS + pi + 1] = pack_f16(v.z, v.w);
        }
    }

    float acc[2][4][4];
#pragma unroll
    for (int m = 0; m < 2; m++)
#pragma unroll
        for (int n = 0; n < 4; n++)
#pragma unroll
            for (int c = 0; c < 4; c++) acc[m][n][c] = 0.f;

    // ---- Phase 1: src_read = relu([mem|feat] @ W_read + b), K=256 ----
    for (int kc = 0; kc < 8; kc++) {
        __syncthreads();
        {   // gather + pack A chunk [64 rows][32 k]
            const float* base = (kc < 4)
                ? node_memory + (size_t)s_src[arow] * D_MEM + kc * 32
                : node_features + (size_t)s_src[arow] * D_FEAT + (kc - 4) * 32;
            const float4* b4 = (const float4*)base;
            float4 va = b4[aq * 2];
            float4 vb = b4[aq * 2 + 1];
            *(uint4*)(sAh + arow * PA + aq * 4) =
                make_uint4(pack_f16(va.x, va.y), pack_f16(va.z, va.w),
                           pack_f16(vb.x, vb.y), pack_f16(vb.z, vb.w));
        }
        {   // copy pre-packed W chunk (L2-resident): 8 u32 per thread
            const unsigned* gh = g_Wf + kc * 2048 + wkp * 128 + wc8;
            unsigned* dh = sWh + wkp * PW + wc8;
            *(uint4*)dh = *(const uint4*)gh;
            *(uint4*)(dh + 4) = *(const uint4*)(gh + 4);
        }
        __syncthreads();
        mma_k32(sAh, PA, sWh, r0, c0, gid, tig, acc);
    }

    // ---- Phase 1 epilogue: bias+relu -> stage kpairs [0,64) ----
    __syncthreads();
#pragma unroll
    for (int mf = 0; mf < 2; mf++) {
        const int ra = r0 + mf * 16 + gid;
#pragma unroll
        for (int nf = 0; nf < 4; nf++) {
            const int col = c0 + nf * 8 + 2 * tig;
            const int pi = col >> 1;
            const float bb0 = b_read[col], bb1 = b_read[col + 1];
            sSh[ra * PS + pi] = pack_f16(fmaxf(acc[mf][nf][0] + bb0, 0.f),
                                         fmaxf(acc[mf][nf][1] + bb1, 0.f));
            sSh[(ra + 8) * PS + pi] = pack_f16(fmaxf(acc[mf][nf][2] + bb0, 0.f),
                                               fmaxf(acc[mf][nf][3] + bb1, 0.f));
        }
    }

    // ---- Phase 2: msgs = relu([src_read|ef|time] @ W_msg + b), K=224 ----
#pragma unroll
    for (int m = 0; m < 2; m++)
#pragma unroll
        for (int n = 0; n < 4; n++)
#pragma unroll
            for (int c = 0; c < 4; c++) acc[m][n][c] = 0.f;

    for (int kc = 0; kc < 7; kc++) {
        __syncthreads();
        {   // copy pre-packed W_msg chunk
            const unsigned* gh = g_Wf + (8 + kc) * 2048 + wkp * 128 + wc8;
            unsigned* dh = sWh + wkp * PW + wc8;
            *(uint4*)dh = *(const uint4*)gh;
            *(uint4*)(dh + 4) = *(const uint4*)(gh + 4);
        }
        __syncthreads();
        mma_k32(sSh + kc * 16, PS, sWh, r0, c0, gid, tig, acc);
    }
    __syncthreads();   // all warps done reading stage before msg overwrite

    // ---- Phase 2 epilogue: msgs -> msgbuf fp32 (reuse stage area) ----
    float* msg = (float*)(su + O_SH);   // [64][STRIDE_M]
#pragma unroll
    for (int mf = 0; mf < 2; mf++) {
        const int ra = r0 + mf * 16 + gid;
#pragma unroll
        for (int nf = 0; nf < 4; nf++) {
            const int col = c0 + nf * 8 + 2 * tig;
            const float b0 = b_msg[col], b1 = b_msg[col + 1];
            msg[ra * STRIDE_M + col]           = fmaxf(acc[mf][nf][0] + b0, 0.f);
            msg[ra * STRIDE_M + col + 1]       = fmaxf(acc[mf][nf][1] + b1, 0.f);
            msg[(ra + 8) * STRIDE_M + col]     = fmaxf(acc[mf][nf][2] + b0, 0.f);
            msg[(ra + 8) * STRIDE_M + col + 1] = fmaxf(acc[mf][nf][3] + b1, 0.f);
        }
    }
    __syncthreads();

    // ---- run-coalesced segment-sum atomics (dest_seg globally sorted) ----
    {
        const int tx = lane;          // 4 cols per lane
        const int e0 = warp * 8;      // 8 warps x 8 edges
        int curd = s_dst[e0];
        float r[4] = {0.f, 0.f, 0.f, 0.f};
        float rl = 0.f;
#pragma unroll
        for (int i = 0; i < 8; i++) {
            const int e = e0 + i;
            const int d = s_dst[e];
            const float4 v = *(const float4*)(msg + e * STRIDE_M + tx * 4);
            if (d != curd) {
                flush_seg(curd, tx, r, rl);
                curd = d;
                r[0] = r[1] = r[2] = r[3] = 0.f;
                rl = 0.f;
            }
            r[0] += v.x; r[1] += v.y; r[2] += v.z; r[3] += v.w;
            rl += 1.f;
        }
        flush_seg(curd, tx, r, rl);
    }

    // ---- node_memory -> out copy slice (rides under compute) ----
    {
        const float4* srcm = (const float4*)node_memory;
        float4* dstm = (float4*)out;
        const long long tot = (long long)N_NODES * D_MEM / 4;
        for (long long i = (long long)blockIdx.x * blockDim.x + tid; i < tot;
             i += (long long)gridDim.x * blockDim.x)
            dstm[i] = srcm[i];
    }
}

// ---------------- dest pipeline (fp32, proven; + self-zeroing) ----------------
#define TILE_E 64

__device__ __forceinline__ void mma_chunk(const float* __restrict__ Asub, int strideA,
                                          const float* __restrict__ Ws,
                                          int ty, int tx, float acc[8][4]) {
#pragma unroll
    for (int k = 0; k < 32; k++) {
        const float* arow = Asub + k * strideA + ty * 8;
        float4 a0 = *(const float4*)(arow);
        float4 a1 = *(const float4*)(arow + 4);
        float4 w  = *(const float4*)(Ws + k * 128 + tx * 4);
        float av[8] = {a0.x, a0.y, a0.z, a0.w, a1.x, a1.y, a1.z, a1.w};
#pragma unroll
        for (int i = 0; i < 8; i++) {
            acc[i][0] = fmaf(av[i], w.x, acc[i][0]);
            acc[i][1] = fmaf(av[i], w.y, acc[i][1]);
            acc[i][2] = fmaf(av[i], w.z, acc[i][2]);
            acc[i][3] = fmaf(av[i], w.w, acc[i][3]);
        }
    }
}

__device__ __forceinline__ void load_w(float* Ws, const float* __restrict__ Wsrc, int tid) {
    const float4* s = (const float4*)Wsrc;
    float4* d = (float4*)Ws;
#pragma unroll
    for (int i = 0; i < 4; i++) d[tid + i * 256] = s[tid + i * 256];
}

__device__ __forceinline__ void zero_acc(float acc[8][4]) {
#pragma unroll
    for (int i = 0; i < 8; i++)
#pragma unroll
        for (int c = 0; c < 4; c++) acc[i][c] = 0.f;
}

__global__ __launch_bounds__(256) void dest_kernel(
    const float* __restrict__ node_memory, const float* __restrict__ node_features,
    const void* __restrict__ node_ids,
    const float* __restrict__ W_read, const float* __restrict__ b_read,
    const float* __restrict__ W_agg, const float* __restrict__ b_agg,
    const float* __restrict__ W_upd, const float* __restrict__ b_upd,
    const float* __restrict__ W_write, const float* __restrict__ b_write,
    float* __restrict__ out) {
    extern __shared__ float sm[];
    float* As = sm;             // [32][64]
    float* Ws = sm + 2048;      // [32][128]
    float* CT = sm + 6144;      // [256][68]
    float* DR = sm + 23552;     // [128][68]
    __shared__ int s_nid[TILE_E];

    const int tid = threadIdx.x;
    const int tx = tid & 31;
    const int ty = tid >> 5;
    const int eL = tid & 63;
    const int kq = tid >> 6;
    const int rbase = blockIdx.x * TILE_E;

    const unsigned* nwid = (const unsigned*)node_ids;
    const int is64 = (nwid[1] == 0u && nwid[3] == 0u);

    if (tid < TILE_E) s_nid[tid] = idx_at(node_ids, rbase + tid, is64);

    float acc[8][4];
    zero_acc(acc);

    for (int kc = 0; kc < 8; kc++) {
        __syncthreads();
        {
            const float* row = (kc < 4)
                ? node_memory + (size_t)s_nid[eL] * D_MEM + kc * 32
                : node_features + (size_t)s_nid[eL] * D_FEAT + (kc - 4) * 32;
            float4 v0 = ((const float4*)row)[kq * 2];
            float4 v1 = ((const float4*)row)[kq * 2 + 1];
            int kb = kq * 8;
            As[(kb + 0) * 64 + eL] = v0.x; As[(kb + 1) * 64 + eL] = v0.y;
            As[(kb + 2) * 64 + eL] = v0.z; As[(kb + 3) * 64 + eL] = v0.w;
            As[(kb + 4) * 64 + eL] = v1.x; As[(kb + 5) * 64 + eL] = v1.y;
            As[(kb + 6) * 64 + eL] = v1.z; As[(kb + 7) * 64 + eL] = v1.w;
        }
        load_w(Ws, W_read + kc * 32 * 128, tid);
        __syncthreads();
        mma_chunk(As, 64, Ws, ty, tx, acc);
    }
    {
        float4 bb = *(const float4*)&b_read[tx * 4];
        __syncthreads();
#pragma unroll
        for (int i = 0; i < 8; i++) {
            int e = ty * 8 + i;
#pragma unroll
            for (int c = 0; c < 4; c++) {
                float bv = (c == 0) ? bb.x : (c == 1) ? bb.y : (c == 2) ? bb.z : bb.w;
                float v = fmaxf(acc[i][c] + bv, 0.f);
                CT[(tx * 4 + c) * 68 + e] = v;
                DR[(tx * 4 + c) * 68 + e] = v;
            }
        }
    }
    {
        int dg = rbase + eL;
        float inv = 1.0f / fmaxf(g_cnt[dg], 1.0f);
        const float4* srcp = (const float4*)(g_msg_sum + (size_t)dg * D_MSG + kq * 32);
#pragma unroll
        for (int j4 = 0; j4 < 8; j4++) {
            float4 v = srcp[j4];
            int kk = 128 + kq * 32 + j4 * 4;
            CT[(kk + 0) * 68 + eL] = v.x * inv; CT[(kk + 1) * 68 + eL] = v.y * inv;
            CT[(kk + 2) * 68 + eL] = v.z * inv; CT[(kk + 3) * 68 + eL] = v.w * inv;
        }
    }
    __syncthreads();
    {
        int dg = rbase + eL;
        float4 z = {0.f, 0.f, 0.f, 0.f};
        float4* p = (float4*)(g_msg_sum + (size_t)dg * D_MSG + kq * 32);
#pragma unroll
        for (int j4 = 0; j4 < 8; j4++) p[j4] = z;
        if (kq == 0) g_cnt[dg] = 0.f;
    }

    zero_acc(acc);
    for (int kc = 0; kc < 8; kc++) {
        __syncthreads();
        load_w(Ws, W_agg + kc * 32 * 128, tid);
        __syncthreads();
        mma_chunk(CT + kc * 32 * 68, 68, Ws, ty, tx, acc);
    }
    __syncthreads();
    {
        float4 ba = *(const float4*)&b_agg[tx * 4];
#pragma unroll
        for (int i = 0; i < 8; i++) {
            int e = ty * 8 + i;
            CT[(tx * 4 + 0) * 68 + e] = fmaxf(acc[i][0] + ba.x, 0.f);
            CT[(tx * 4 + 1) * 68 + e] = fmaxf(acc[i][1] + ba.y, 0.f);
            CT[(tx * 4 + 2) * 68 + e] = fmaxf(acc[i][2] + ba.z, 0.f);
            CT[(tx * 4 + 3) * 68 + e] = fmaxf(acc[i][3] + ba.w, 0.f);
        }
#pragma unroll
        for (int j = 0; j < 32; j++) {
            int row = kq * 32 + j;
            CT[(128 + row) * 68 + eL] = DR[row * 68 + eL];
        }
    }

    zero_acc(acc);
    for (int kc = 0; kc < 8; kc++) {
        __syncthreads();
        load_w(Ws, W_upd + kc * 32 * 128, tid);
        __syncthreads();
        mma_chunk(CT + kc * 32 * 68, 68, Ws, ty, tx, acc);
    }
    __syncthreads();
    {
        float4 bu = *(const float4*)&b_upd[tx * 4];
#pragma unroll
        for (int i = 0; i < 8; i++) {
            int e = ty * 8 + i;
            DR[(tx * 4 + 0) * 68 + e] = fmaxf(acc[i][0] + bu.x, 0.f);
            DR[(tx * 4 + 1) * 68 + e] = fmaxf(acc[i][1] + bu.y, 0.f);
            DR[(tx * 4 + 2) * 68 + e] = fmaxf(acc[i][2] + bu.z, 0.f);
            DR[(tx * 4 + 3) * 68 + e] = fmaxf(acc[i][3] + bu.w, 0.f);
        }
    }

    zero_acc(acc);
    for (int kc = 0; kc < 4; kc++) {
        __syncthreads();
        load_w(Ws, W_write + kc * 32 * 128, tid);
        __syncthreads();
        mma_chunk(DR + kc * 32 * 68, 68, Ws, ty, tx, acc);
    }
    {
        float4 bw = *(const float4*)&b_write[tx * 4];
#pragma unroll
        for (int i = 0; i < 8; i++) {
            int e = ty * 8 + i;
            float4 o;
            o.x = tanhf(acc[i][0] + bw.x);
            o.y = tanhf(acc[i][1] + bw.y);
            o.z = tanhf(acc[i][2] + bw.z);
            o.w = tanhf(acc[i][3] + bw.w);
            *(float4*)(out + (size_t)s_nid[e] * D_MEM + tx * 4) = o;
        }
    }
}

// ---------------- launch ------------------------------------------------------
#define DEST_SMEM ((2048 + 4096 + 256 * 68 + 128 * 68) * 4)

extern "C" void kernel_launch(void* const* d_in, const int* in_sizes, int n_in,
                              void* d_out, int out_size) {
    const float* node_memory   = (const float*)d_in[0];
    const float* node_features = (const float*)d_in[1];
    const float* edge_features = (const float*)d_in[2];
    const float* time_encoding = (const float*)d_in[3];
    const void*  node_ids      = d_in[4];
    const void*  source_ids    = d_in[5];
    const void*  edge_ids      = d_in[6];
    const void*  dest_seg      = d_in[7];
    const float* W_read  = (const float*)d_in[8];
    const float* b_read  = (const float*)d_in[9];
    const float* W_msg   = (const float*)d_in[10];
    const float* b_msg   = (const float*)d_in[11];
    const float* W_agg   = (const float*)d_in[12];
    const float* b_agg   = (const float*)d_in[13];
    const float* W_upd   = (const float*)d_in[14];
    const float* b_upd   = (const float*)d_in[15];
    const float* W_write = (const float*)d_in[16];
    const float* b_write = (const float*)d_in[17];
    float* out = (float*)d_out;

    cudaFuncSetAttribute(edge_kernel, cudaFuncAttributeMaxDynamicSharedMemorySize, EDGE_SMEM);
    cudaFuncSetAttribute(dest_kernel, cudaFuncAttributeMaxDynamicSharedMemorySize, DEST_SMEM);

    prep_kernel<<<120, 256>>>(W_read, W_msg);

    edge_kernel<<<N_EDGE / 64, 256, EDGE_SMEM>>>(
        node_memory, node_features, edge_features, time_encoding, node_ids,
        source_ids, edge_ids, dest_seg, b_read, b_msg, out);

    dest_kernel<<<N_DEST / TILE_E, 256, DEST_SMEM>>>(
        node_memory, node_features, node_ids,
        W_read, b_read, W_agg, b_agg, W_upd, b_upd, W_write, b_write, out);
}

// round 10
// speedup vs baseline: 2.3682x; 1.1549x over previous
#include <cuda_runtime.h>
#include <cuda_fp16.h>
#include <math.h>

#define N_NODES 200000
#define N_DEST  8192
#define N_EDGE  262144
#define D_MEM   128
#define D_FEAT  128
#define D_EDGE  64
#define D_TIME  32
#define D_MSG   128

// ---------------- scratch (device globals: allocation-free) ------------------
__device__ float g_msg_sum[N_DEST * D_MSG];   // zero-init; dest_kernel re-zeroes
__device__ float g_cnt[N_DEST];
// pre-packed fp16x2 W chunks [chunk][kp][128]:
// 0-7 W_read, 8-14 W_msg, 15-22 W_agg, 23-30 W_upd, 31-34 W_write
__device__ unsigned g_Wf[35 * 2048];

__device__ __forceinline__ int idx_at(const void* p, long long i, int is64) {
    return is64 ? (int)((const long long*)p)[i] : ((const int*)p)[i];
}

// ---------------- fp16 pack / mma ----------------------------------------------
__device__ __forceinline__ unsigned pack_f16(float x0, float x1) {
    unsigned r;
    asm("cvt.rn.f16x2.f32 %0, %1, %2;" : "=r"(r) : "f"(x1), "f"(x0));
    return r;
}

__device__ __forceinline__ void mma_f16(float* c, const unsigned* a, const unsigned* b) {
    asm volatile(
        "mma.sync.aligned.m16n8k16.row.col.f32.f16.f16.f32 "
        "{%0,%1,%2,%3},{%4,%5,%6,%7},{%8,%9},{%0,%1,%2,%3};"
        : "+f"(c[0]), "+f"(c[1]), "+f"(c[2]), "+f"(c[3])
        : "r"(a[0]), "r"(a[1]), "r"(a[2]), "r"(a[3]), "r"(b[0]), "r"(b[1]));
}

// ---------------- prep: pre-pack ALL weights into fp16x2 ----------------------
__global__ void prep_kernel(const float* __restrict__ W_read,
                            const float* __restrict__ W_msg,
                            const float* __restrict__ W_agg,
                            const float* __restrict__ W_upd,
                            const float* __restrict__ W_write) {
    const int idx = blockIdx.x * blockDim.x + threadIdx.x;
    if (idx >= 35 * 2048) return;
    const int chunk = idx >> 11;
    const int kp = (idx >> 7) & 15;
    const int c = idx & 127;
    const float* W;
    int cl;
    if (chunk < 8)       { W = W_read;  cl = chunk; }
    else if (chunk < 15) { W = W_msg;   cl = chunk - 8; }
    else if (chunk < 23) { W = W_agg;   cl = chunk - 15; }
    else if (chunk < 31) { W = W_upd;   cl = chunk - 23; }
    else                 { W = W_write; cl = chunk - 31; }
    const int row = cl * 32 + 2 * kp;
    g_Wf[idx] = pack_f16(W[row * 128 + c], W[(row + 1) * 128 + c]);
}

// ---------------- shared mma chunk: 1-term fp16, warp tile 32x32 --------------
#define PW 136   // W stride (proven)

__device__ __forceinline__ void mma_k32(const unsigned* __restrict__ Ah, int strideA,
                                        const unsigned* __restrict__ Wh,
                                        int r0, int c0, int gid, int tig,
                                        float acc[2][4][4]) {
#pragma unroll
    for (int half = 0; half < 2; half++) {
        const int kb = half * 8;
        unsigned ah[2][4];
#pragma unroll
        for (int mf = 0; mf < 2; mf++) {
            const int ra = r0 + mf * 16 + gid;
            ah[mf][0] = Ah[ra * strideA + kb + tig];
            ah[mf][1] = Ah[(ra + 8) * strideA + kb + tig];
            ah[mf][2] = Ah[ra * strideA + kb + tig + 4];
            ah[mf][3] = Ah[(ra + 8) * strideA + kb + tig + 4];
        }
#pragma unroll
        for (int nf = 0; nf < 4; nf++) {
            const int col = c0 + nf * 8 + gid;
            unsigned bh[2];
            bh[0] = Wh[(kb + tig) * PW + col];
            bh[1] = Wh[(kb + tig + 4) * PW + col];
#pragma unroll
            for (int mf = 0; mf < 2; mf++) mma_f16(acc[mf][nf], ah[mf], bh);
        }
    }
}

__device__ __forceinline__ void zacc(float acc[2][4][4]) {
#pragma unroll
    for (int m = 0; m < 2; m++)
#pragma unroll
        for (int n = 0; n < 4; n++)
#pragma unroll
            for (int c = 0; c < 4; c++) acc[m][n][c] = 0.f;
}

// ---------------- edge kernel (proven R9: 64-edge tile, 1-term fp16) ----------
#define PA 20
#define PS 116
#define STRIDE_M 132

#define O_AH 0
#define O_WH 1280
#define O_SH 3456
#define EDGE_U32 (3456 + 8448)
#define EDGE_SMEM (EDGE_U32 * 4)

__device__ __forceinline__ void flush_seg(int d, int tx, const float* r, float rl) {
    float* p = g_msg_sum + (size_t)d * D_MSG + tx * 4;
    atomicAdd(p + 0, r[0]);
    atomicAdd(p + 1, r[1]);
    atomicAdd(p + 2, r[2]);
    atomicAdd(p + 3, r[3]);
    if (tx == 0) atomicAdd(&g_cnt[d], rl);
}

__global__ __launch_bounds__(256, 3) void edge_kernel(
    const float* __restrict__ node_memory, const float* __restrict__ node_features,
    const float* __restrict__ edge_features, const float* __restrict__ time_encoding,
    const void* __restrict__ node_ids,
    const void* __restrict__ source_ids, const void* __restrict__ edge_ids,
    const void* __restrict__ dest_seg,
    const float* __restrict__ b_read, const float* __restrict__ b_msg,
    float* __restrict__ out) {
    extern __shared__ unsigned su[];
    unsigned* sAh = su + O_AH;
    unsigned* sWh = su + O_WH;
    unsigned* sSh = su + O_SH;
    __shared__ int s_src[64], s_eid[64], s_dst[64];

    const int tid = threadIdx.x;
    const int lane = tid & 31;
    const int warp = tid >> 5;
    const int gid = lane >> 2;
    const int tig = lane & 3;
    const int r0 = (warp >> 2) * 32;
    const int c0 = (warp & 3) * 32;
    const long long ebase = (long long)blockIdx.x * 64;

    const unsigned* nwid = (const unsigned*)node_ids;
    const int is64 = (nwid[1] == 0u && nwid[3] == 0u);

    if (tid < 64) {
        s_src[tid] = idx_at(source_ids, ebase + tid, is64);
        s_eid[tid] = idx_at(edge_ids, ebase + tid, is64);
        s_dst[tid] = idx_at(dest_seg, ebase + tid, is64);
    }
    __syncthreads();

    const int arow = tid >> 2;
    const int aq = tid & 3;
    const int wkp = tid >> 4;
    const int wc8 = (tid & 15) * 8;

    // prefill stage kpairs [64,112): edge feats, time
    {
        const float4* ef = (const float4*)(edge_features + (size_t)s_eid[arow] * D_EDGE);
#pragma unroll
        for (int j = 0; j < 4; j++) {
            float4 v = ef[aq * 4 + j];
            const int pi = 64 + aq * 8 + 2 * j;
            sSh[arow * PS + pi] = pack_f16(v.x, v.y);
            sSh[arow * PS + pi + 1] = pack_f16(v.z, v.w);
        }
        const float4* tf = (const float4*)(time_encoding + (ebase + arow) * D_TIME);
#pragma unroll
        for (int j = 0; j < 2; j++) {
            float4 v = tf[aq * 2 + j];
            const int pi = 96 + aq * 4 + 2 * j;
            sSh[arow * PS + pi] = pack_f16(v.x, v.y);
            sSh[arow * PS + pi + 1] = pack_f16(v.z, v.w);
        }
    }

    float acc[2][4][4];
    zacc(acc);

    // Phase 1: src_read, K=256
    for (int kc = 0; kc < 8; kc++) {
        __syncthreads();
        {
            const float* base = (kc < 4)
                ? node_memory + (size_t)s_src[arow] * D_MEM + kc * 32
                : node_features + (size_t)s_src[arow] * D_FEAT + (kc - 4) * 32;
            const float4* b4 = (const float4*)base;
            float4 va = b4[aq * 2];
            float4 vb = b4[aq * 2 + 1];
            *(uint4*)(sAh + arow * PA + aq * 4) =
                make_uint4(pack_f16(va.x, va.y), pack_f16(va.z, va.w),
                           pack_f16(vb.x, vb.y), pack_f16(vb.z, vb.w));
        }
        {
            const unsigned* gh = g_Wf + kc * 2048 + wkp * 128 + wc8;
            unsigned* dh = sWh + wkp * PW + wc8;
            *(uint4*)dh = *(const uint4*)gh;
            *(uint4*)(dh + 4) = *(const uint4*)(gh + 4);
        }
        __syncthreads();
        mma_k32(sAh, PA, sWh, r0, c0, gid, tig, acc);
    }

    // Phase 1 epilogue -> stage kpairs [0,64)
    __syncthreads();
#pragma unroll
    for (int mf = 0; mf < 2; mf++) {
        const int ra = r0 + mf * 16 + gid;
#pragma unroll
        for (int nf = 0; nf < 4; nf++) {
            const int col = c0 + nf * 8 + 2 * tig;
            const int pi = col >> 1;
            const float bb0 = b_read[col], bb1 = b_read[col + 1];
            sSh[ra * PS + pi] = pack_f16(fmaxf(acc[mf][nf][0] + bb0, 0.f),
                                         fmaxf(acc[mf][nf][1] + bb1, 0.f));
            sSh[(ra + 8) * PS + pi] = pack_f16(fmaxf(acc[mf][nf][2] + bb0, 0.f),
                                               fmaxf(acc[mf][nf][3] + bb1, 0.f));
        }
    }

    // Phase 2: msgs, K=224
    zacc(acc);
    for (int kc = 0; kc < 7; kc++) {
        __syncthreads();
        {
            const unsigned* gh = g_Wf + (8 + kc) * 2048 + wkp * 128 + wc8;
            unsigned* dh = sWh + wkp * PW + wc8;
            *(uint4*)dh = *(const uint4*)gh;
            *(uint4*)(dh + 4) = *(const uint4*)(gh + 4);
        }
        __syncthreads();
        mma_k32(sSh + kc * 16, PS, sWh, r0, c0, gid, tig, acc);
    }
    __syncthreads();

    // Phase 2 epilogue: msgs -> msgbuf fp32 (reuse stage)
    float* msg = (float*)(su + O_SH);
#pragma unroll
    for (int mf = 0; mf < 2; mf++) {
        const int ra = r0 + mf * 16 + gid;
#pragma unroll
        for (int nf = 0; nf < 4; nf++) {
            const int col = c0 + nf * 8 + 2 * tig;
            const float b0 = b_msg[col], b1 = b_msg[col + 1];
            msg[ra * STRIDE_M + col]           = fmaxf(acc[mf][nf][0] + b0, 0.f);
            msg[ra * STRIDE_M + col + 1]       = fmaxf(acc[mf][nf][1] + b1, 0.f);
            msg[(ra + 8) * STRIDE_M + col]     = fmaxf(acc[mf][nf][2] + b0, 0.f);
            msg[(ra + 8) * STRIDE_M + col + 1] = fmaxf(acc[mf][nf][3] + b1, 0.f);
        }
    }
    __syncthreads();

    // run-coalesced segment-sum atomics
    {
        const int tx = lane;
        const int e0 = warp * 8;
        int curd = s_dst[e0];
        float r[4] = {0.f, 0.f, 0.f, 0.f};
        float rl = 0.f;
#pragma unroll
        for (int i = 0; i < 8; i++) {
            const int e = e0 + i;
            const int d = s_dst[e];
            const float4 v = *(const float4*)(msg + e * STRIDE_M + tx * 4);
            if (d != curd) {
                flush_seg(curd, tx, r, rl);
                curd = d;
                r[0] = r[1] = r[2] = r[3] = 0.f;
                rl = 0.f;
            }
            r[0] += v.x; r[1] += v.y; r[2] += v.z; r[3] += v.w;
            rl += 1.f;
        }
        flush_seg(curd, tx, r, rl);
    }

    // node_memory -> out copy slice
    {
        const float4* srcm = (const float4*)node_memory;
        float4* dstm = (float4*)out;
        const long long tot = (long long)N_NODES * D_MEM / 4;
        for (long long i = (long long)blockIdx.x * blockDim.x + tid; i < tot;
             i += (long long)gridDim.x * blockDim.x)
            dstm[i] = srcm[i];
    }
}

// ---------------- dest kernel: fp16 MMA, 64-row tile ---------------------------
#define DPA 20
#define DPS 132   // stage stride (132 mod 32 = 4, conflict-free)
#define DPD 68    // dst_read copy stride (68 mod 32 = 4)

#define DO_A 0        // 64*20  = 1280
#define DO_W 1280     // 16*136 = 2176
#define DO_S 3456     // 64*132 = 8448
#define DO_D 11904    // 64*68  = 4352
#define DEST_U32 16256
#define DEST_SMEM (DEST_U32 * 4)   // 65024 B

__global__ __launch_bounds__(256) void dest_kernel(
    const float* __restrict__ node_memory, const float* __restrict__ node_features,
    const void* __restrict__ node_ids,
    const float* __restrict__ b_read, const float* __restrict__ b_agg,
    const float* __restrict__ b_upd, const float* __restrict__ b_write,
    float* __restrict__ out) {
    extern __shared__ unsigned su[];
    unsigned* sA = su + DO_A;
    unsigned* sW = su + DO_W;
    unsigned* sS = su + DO_S;
    unsigned* sD2 = su + DO_D;
    __shared__ int s_nid[64];

    const int tid = threadIdx.x;
    const int lane = tid & 31;
    const int warp = tid >> 5;
    const int gid = lane >> 2;
    const int tig = lane & 3;
    const int r0 = (warp >> 2) * 32;
    const int c0 = (warp & 3) * 32;
    const int rbase = blockIdx.x * 64;

    const unsigned* nwid = (const unsigned*)node_ids;
    const int is64 = (nwid[1] == 0u && nwid[3] == 0u);

    if (tid < 64) s_nid[tid] = idx_at(node_ids, rbase + tid, is64);
    __syncthreads();

    const int arow = tid >> 2;
    const int aq = tid & 3;
    const int wkp = tid >> 4;
    const int wc8 = (tid & 15) * 8;

    float acc[2][4][4];

    // ---- GEMM 1: dst_read = relu([mem|feat] @ W_read + b), K=256 ----
    zacc(acc);
    for (int kc = 0; kc < 8; kc++) {
        __syncthreads();
        {
            const float* base = (kc < 4)
                ? node_memory + (size_t)s_nid[arow] * D_MEM + kc * 32
                : node_features + (size_t)s_nid[arow] * D_FEAT + (kc - 4) * 32;
            const float4* b4 = (const float4*)base;
            float4 va = b4[aq * 2];
            float4 vb = b4[aq * 2 + 1];
            *(uint4*)(sA + arow * DPA + aq * 4) =
                make_uint4(pack_f16(va.x, va.y), pack_f16(va.z, va.w),
                           pack_f16(vb.x, vb.y), pack_f16(vb.z, vb.w));
        }
        {
            const unsigned* gh = g_Wf + kc * 2048 + wkp * 128 + wc8;
            unsigned* dh = sW + wkp * PW + wc8;
            *(uint4*)dh = *(const uint4*)gh;
            *(uint4*)(dh + 4) = *(const uint4*)(gh + 4);
        }
        __syncthreads();
        mma_k32(sA, DPA, sW, r0, c0, gid, tig, acc);
    }
    __syncthreads();
    // epilogue: dst_read -> sS kp[0,64) and sD2
#pragma unroll
    for (int mf = 0; mf < 2; mf++) {
        const int ra = r0 + mf * 16 + gid;
#pragma unroll
        for (int nf = 0; nf < 4; nf++) {
            const int col = c0 + nf * 8 + 2 * tig;
            const int pi = col >> 1;
            const float bb0 = b_read[col], bb1 = b_read[col + 1];
            unsigned u0 = pack_f16(fmaxf(acc[mf][nf][0] + bb0, 0.f),
                                   fmaxf(acc[mf][nf][1] + bb1, 0.f));
            unsigned u1 = pack_f16(fmaxf(acc[mf][nf][2] + bb0, 0.f),
                                   fmaxf(acc[mf][nf][3] + bb1, 0.f));
            sS[ra * DPS + pi] = u0;       sD2[ra * DPD + pi] = u0;
            sS[(ra + 8) * DPS + pi] = u1; sD2[(ra + 8) * DPD + pi] = u1;
        }
    }

    // ---- msg_mean -> sS kp[64,128); re-zero scratch ----
    {
        const int dg = rbase + arow;
        const float inv = 1.0f / fmaxf(g_cnt[dg], 1.0f);
        const float4* sp = (const float4*)(g_msg_sum + (size_t)dg * D_MSG + aq * 32);
#pragma unroll
        for (int j4 = 0; j4 < 8; j4++) {
            float4 v = sp[j4];
            const int pi = 64 + aq * 16 + 2 * j4;
            sS[arow * DPS + pi] = pack_f16(v.x * inv, v.y * inv);
            sS[arow * DPS + pi + 1] = pack_f16(v.z * inv, v.w * inv);
        }
        float4 z = {0.f, 0.f, 0.f, 0.f};
        float4* p = (float4*)(g_msg_sum + (size_t)dg * D_MSG + aq * 32);
#pragma unroll
        for (int j4 = 0; j4 < 8; j4++) p[j4] = z;
        if (aq == 0) g_cnt[dg] = 0.f;
    }

    // ---- GEMM 2: agg = relu([dst_read|msg_mean] @ W_agg + b), K=256 ----
    zacc(acc);
    for (int kc = 0; kc < 8; kc++) {
        __syncthreads();
        {
            const unsigned* gh = g_Wf + (15 + kc) * 2048 + wkp * 128 + wc8;
            unsigned* dh = sW + wkp * PW + wc8;
            *(uint4*)dh = *(const uint4*)gh;
            *(uint4*)(dh + 4) = *(const uint4*)(gh + 4);
        }
        __syncthreads();
        mma_k32(sS + kc * 16, DPS, sW, r0, c0, gid, tig, acc);
    }
    __syncthreads();
    // epilogue: agg -> sS kp[0,64)
#pragma unroll
    for (int mf = 0; mf < 2; mf++) {
        const int ra = r0 + mf * 16 + gid;
#pragma unroll
        for (int nf = 0; nf < 4; nf++) {
            const int col = c0 + nf * 8 + 2 * tig;
            const int pi = col >> 1;
            const float bb0 = b_agg[col], bb1 = b_agg[col + 1];
            sS[ra * DPS + pi] = pack_f16(fmaxf(acc[mf][nf][0] + bb0, 0.f),
                                         fmaxf(acc[mf][nf][1] + bb1, 0.f));
            sS[(ra + 8) * DPS + pi] = pack_f16(fmaxf(acc[mf][nf][2] + bb0, 0.f),
                                               fmaxf(acc[mf][nf][3] + bb1, 0.f));
        }
    }

    // ---- GEMM 3: upd = relu([agg|dst_read] @ W_upd + b), K=256 ----
    // chunks 0-3 read agg from sS; chunks 4-7 read dst_read from sD2
    zacc(acc);
    for (int kc = 0; kc < 8; kc++) {
        __syncthreads();
        {
            const unsigned* gh = g_Wf + (23 + kc) * 2048 + wkp * 128 + wc8;
            unsigned* dh = sW + wkp * PW + wc8;
            *(uint4*)dh = *(const uint4*)gh;
            *(uint4*)(dh + 4) = *(const uint4*)(gh + 4);
        }
        __syncthreads();
        if (kc < 4)
            mma_k32(sS + kc * 16, DPS, sW, r0, c0, gid, tig, acc);
        else
            mma_k32(sD2 + (kc - 4) * 16, DPD, sW, r0, c0, gid, tig, acc);
    }
    __syncthreads();
    // epilogue: upd -> sS kp[0,64)
#pragma unroll
    for (int mf = 0; mf < 2; mf++) {
        const int ra = r0 + mf * 16 + gid;
#pragma unroll
        for (int nf = 0; nf < 4; nf++) {
            const int col = c0 + nf * 8 + 2 * tig;
            const int pi = col >> 1;
            const float bb0 = b_upd[col], bb1 = b_upd[col + 1];
            sS[ra * DPS + pi] = pack_f16(fmaxf(acc[mf][nf][0] + bb0, 0.f),
                                         fmaxf(acc[mf][nf][1] + bb1, 0.f));
            sS[(ra + 8) * DPS + pi] = pack_f16(fmaxf(acc[mf][nf][2] + bb0, 0.f),
                                               fmaxf(acc[mf][nf][3] + bb1, 0.f));
        }
    }

    // ---- GEMM 4: write = tanh(upd @ W_write + b), K=128; scatter ----
    zacc(acc);
    for (int kc = 0; kc < 4; kc++) {
        __syncthreads();
        {
            const unsigned* gh = g_Wf + (31 + kc) * 2048 + wkp * 128 + wc8;
            unsigned* dh = sW + wkp * PW + wc8;
            *(uint4*)dh = *(const uint4*)gh;
            *(uint4*)(dh + 4) = *(const uint4*)(gh + 4);
        }
        __syncthreads();
        mma_k32(sS + kc * 16, DPS, sW, r0, c0, gid, tig, acc);
    }
#pragma unroll
    for (int mf = 0; mf < 2; mf++) {
        const int ra = r0 + mf * 16 + gid;
        const int n0 = s_nid[ra], n1 = s_nid[ra + 8];
#pragma unroll
        for (int nf = 0; nf < 4; nf++) {
            const int col = c0 + nf * 8 + 2 * tig;
            const float bb0 = b_write[col], bb1 = b_write[col + 1];
            float2 o0, o1;
            o0.x = tanhf(acc[mf][nf][0] + bb0);
            o0.y = tanhf(acc[mf][nf][1] + bb1);
            o1.x = tanhf(acc[mf][nf][2] + bb0);
            o1.y = tanhf(acc[mf][nf][3] + bb1);
            *(float2*)(out + (size_t)n0 * D_MEM + col) = o0;
            *(float2*)(out + (size_t)n1 * D_MEM + col) = o1;
        }
    }
}

// ---------------- launch ------------------------------------------------------
extern "C" void kernel_launch(void* const* d_in, const int* in_sizes, int n_in,
                              void* d_out, int out_size) {
    const float* node_memory   = (const float*)d_in[0];
    const float* node_features = (const float*)d_in[1];
    const float* edge_features = (const float*)d_in[2];
    const float* time_encoding = (const float*)d_in[3];
    const void*  node_ids      = d_in[4];
    const void*  source_ids    = d_in[5];
    const void*  edge_ids      = d_in[6];
    const void*  dest_seg      = d_in[7];
    const float* W_read  = (const float*)d_in[8];
    const float* b_read  = (const float*)d_in[9];
    const float* W_msg   = (const float*)d_in[10];
    const float* b_msg   = (const float*)d_in[11];
    const float* W_agg   = (const float*)d_in[12];
    const float* b_agg   = (const float*)d_in[13];
    const float* W_upd   = (const float*)d_in[14];
    const float* b_upd   = (const float*)d_in[15];
    const float* W_write = (const float*)d_in[16];
    const float* b_write = (const float*)d_in[17];
    float* out = (float*)d_out;

    cudaFuncSetAttribute(edge_kernel, cudaFuncAttributeMaxDynamicSharedMemorySize, EDGE_SMEM);
    cudaFuncSetAttribute(dest_kernel, cudaFuncAttributeMaxDynamicSharedMemorySize, DEST_SMEM);

    prep_kernel<<<280, 256>>>(W_read, W_msg, W_agg, W_upd, W_write);

    edge_kernel<<<N_EDGE / 64, 256, EDGE_SMEM>>>(
        node_memory, node_features, edge_features, time_encoding, node_ids,
        source_ids, edge_ids, dest_seg, b_read, b_msg, out);

    dest_kernel<<<N_DEST / 64, 256, DEST_SMEM>>>(
        node_memory, node_features, node_ids,
        b_read, b_agg, b_upd, b_write, out);
}